// round 1
// baseline (speedup 1.0000x reference)
#include <cuda_runtime.h>
#include <math.h>

#define NNODE 150000
#define NEDGE 300000
#define NEA   450000   // NEDGE + NNODE (with self loops)
#define NB    4096
#define DIN   155
#define DE    6
#define HID   256
#define NH    4
#define CC    64
#define NLAY  4
#define NEGSL 0.2f
#define EPSV  1e-5f

// ---------------- scratch (static device globals; no allocation) -------------
__device__ float g_h0[NNODE*HID];
__device__ float g_h1[NNODE*HID];
__device__ float g_xh[NNODE*HID];
__device__ float g_out[NNODE*HID];
__device__ float g_lattr[NNODE*DE];
__device__ float g_deg[NNODE];
__device__ float g_as[NNODE*NH];
__device__ float g_ad[NNODE*NH];
__device__ float g_lg[NEA*NH];
__device__ float g_m[NNODE*NH];
__device__ float g_dn[NNODE*NH];
__device__ float g_we[DE*NH];
__device__ float g_bnsum[2*HID];
__device__ float g_bnab[2*HID];
__device__ float g_pool[NB*HID];
__device__ float g_z1[NB*128];
__device__ float g_z2[NB*64];

// ---------------- helpers ----------------------------------------------------
__device__ __forceinline__ void atomicMaxF(float* addr, float v) {
    if (v >= 0.f) atomicMax((int*)addr, __float_as_int(v));
    else          atomicMin((unsigned int*)addr, (unsigned int)__float_as_int(v));
}

// ---------------- generic tiled SGEMM: C = relu?(A[M,K] @ B[K,N] + bias) -----
__global__ __launch_bounds__(256)
void sgemm_kernel(const float* __restrict__ A, const float* __restrict__ B,
                  const float* __restrict__ bias, float* __restrict__ C,
                  int M, int K, int N, int doRelu)
{
    const int BM = 128, BN = 128, BK = 8;
    __shared__ float As[BK][BM + 4];
    __shared__ float Bs[BK][BN];
    int tid = threadIdx.x;
    int bm = blockIdx.y * BM, bn = blockIdx.x * BN;
    int ty = tid >> 4, tx = tid & 15;
    float acc[8][8];
#pragma unroll
    for (int i = 0; i < 8; i++)
#pragma unroll
        for (int j = 0; j < 8; j++) acc[i][j] = 0.f;

    for (int k0 = 0; k0 < K; k0 += BK) {
#pragma unroll
        for (int i = 0; i < 4; i++) {
            int l = tid + i * 256;
            int r = l >> 3, c = l & 7;
            int gr = bm + r, gc = k0 + c;
            As[c][r] = (gr < M && gc < K) ? A[(size_t)gr * K + gc] : 0.f;
        }
#pragma unroll
        for (int i = 0; i < 4; i++) {
            int l = tid + i * 256;
            int r = l >> 7, c = l & 127;
            int gr = k0 + r, gc = bn + c;
            Bs[r][c] = (gr < K && gc < N) ? B[(size_t)gr * N + gc] : 0.f;
        }
        __syncthreads();
#pragma unroll
        for (int k = 0; k < BK; k++) {
            float4 av0 = *(const float4*)&As[k][ty * 8];
            float4 av1 = *(const float4*)&As[k][ty * 8 + 4];
            float4 bv0 = *(const float4*)&Bs[k][tx * 8];
            float4 bv1 = *(const float4*)&Bs[k][tx * 8 + 4];
            float ar[8] = {av0.x, av0.y, av0.z, av0.w, av1.x, av1.y, av1.z, av1.w};
            float br[8] = {bv0.x, bv0.y, bv0.z, bv0.w, bv1.x, bv1.y, bv1.z, bv1.w};
#pragma unroll
            for (int i = 0; i < 8; i++)
#pragma unroll
                for (int j = 0; j < 8; j++) acc[i][j] += ar[i] * br[j];
        }
        __syncthreads();
    }
#pragma unroll
    for (int i = 0; i < 8; i++) {
        int gr = bm + ty * 8 + i;
        if (gr >= M) continue;
#pragma unroll
        for (int j = 0; j < 8; j++) {
            int gc = bn + tx * 8 + j;
            if (gc >= N) continue;
            float v = acc[i][j];
            if (bias) v += bias[gc];
            if (doRelu) v = fmaxf(v, 0.f);
            C[(size_t)gr * N + gc] = v;
        }
    }
}

// ---------------- self-loop attr (mean of incoming edge feats) ---------------
__global__ void edge_deg_kernel(const int* __restrict__ ei, const float* __restrict__ eattr,
                                float* __restrict__ deg, float* __restrict__ lattr)
{
    int e = blockIdx.x * blockDim.x + threadIdx.x;
    if (e >= NEDGE) return;
    int d = ei[NEDGE + e];
    atomicAdd(&deg[d], 1.f);
#pragma unroll
    for (int k = 0; k < DE; k++) atomicAdd(&lattr[d * DE + k], eattr[e * DE + k]);
}

__global__ void loop_norm_kernel(const float* __restrict__ deg, float* __restrict__ lattr)
{
    int n = blockIdx.x * blockDim.x + threadIdx.x;
    if (n >= NNODE) return;
    float inv = 1.f / fmaxf(deg[n], 1.f);
#pragma unroll
    for (int k = 0; k < DE; k++) lattr[n * DE + k] *= inv;
}

// ---------------- per-layer: contracted edge attention weights ---------------
// we[k][h] = sum_c edge_W[k, h*C+c] * att_edge[h, c]
__global__ void we_kernel(const float* __restrict__ eW, const float* __restrict__ aE,
                          float* __restrict__ we)
{
    int t = threadIdx.x;
    if (t >= DE * NH) return;
    int k = t >> 2, hh = t & 3;
    float s = 0.f;
    for (int c = 0; c < CC; c++) s += eW[k * HID + hh * CC + c] * aE[hh * CC + c];
    we[t] = s;
}

// ---------------- node attention scalars a_s, a_d ----------------------------
__global__ void attn_node_kernel(const float* __restrict__ xh, const float* __restrict__ wsrc,
                                 const float* __restrict__ wdst,
                                 float* __restrict__ a_s, float* __restrict__ a_d)
{
    int gw = (blockIdx.x * blockDim.x + threadIdx.x) >> 5;
    int lane = threadIdx.x & 31;
    if (gw >= NNODE * NH) return;
    int n = gw >> 2, hh = gw & 3;
    const float* row = xh + (size_t)n * HID + hh * CC;
    const float* ws = wsrc + hh * CC;
    const float* wd = wdst + hh * CC;
    float v0 = row[lane], v1 = row[lane + 32];
    float s = v0 * ws[lane] + v1 * ws[lane + 32];
    float d = v0 * wd[lane] + v1 * wd[lane + 32];
#pragma unroll
    for (int o = 16; o; o >>= 1) {
        s += __shfl_xor_sync(0xFFFFFFFFu, s, o);
        d += __shfl_xor_sync(0xFFFFFFFFu, d, o);
    }
    if (lane == 0) { a_s[gw] = s; a_d[gw] = d; }
}

// ---------------- reset m / denom / bn sums ----------------------------------
__global__ void layer_reset_kernel(float* __restrict__ m, float* __restrict__ dn,
                                   float* __restrict__ bnsum)
{
    int idx = blockIdx.x * blockDim.x + threadIdx.x;
    if (idx < NNODE * NH) { m[idx] = -INFINITY; dn[idx] = 0.f; }
    if (idx < 2 * HID) bnsum[idx] = 0.f;
}

// ---------------- edge pass 1: logits + segment max --------------------------
__global__ void edge_logits_kernel(const int* __restrict__ ei, const float* __restrict__ eattr,
                                   const float* __restrict__ lattr, const float* __restrict__ we,
                                   const float* __restrict__ a_s, const float* __restrict__ a_d,
                                   float* __restrict__ lg, float* __restrict__ m)
{
    int idx = blockIdx.x * blockDim.x + threadIdx.x;
    if (idx >= NEA * NH) return;
    int ea = idx >> 2, hh = idx & 3;
    int s, d; const float* at;
    if (ea < NEDGE) { s = ei[ea]; d = ei[NEDGE + ea]; at = eattr + (size_t)ea * DE; }
    else            { s = d = ea - NEDGE;             at = lattr + (size_t)(ea - NEDGE) * DE; }
    float ae = 0.f;
#pragma unroll
    for (int k = 0; k < DE; k++) ae += at[k] * we[k * NH + hh];
    float v = a_s[s * NH + hh] + a_d[d * NH + hh] + ae;
    v = v > 0.f ? v : NEGSL * v;
    lg[idx] = v;
    atomicMaxF(&m[d * NH + hh], v);
}

// ---------------- edge pass 2: exp + segment sum -----------------------------
__global__ void edge_exp_kernel(const int* __restrict__ ei, float* __restrict__ lg,
                                const float* __restrict__ m, float* __restrict__ dn)
{
    int idx = blockIdx.x * blockDim.x + threadIdx.x;
    if (idx >= NEA * NH) return;
    int ea = idx >> 2, hh = idx & 3;
    int d = (ea < NEDGE) ? ei[NEDGE + ea] : (ea - NEDGE);
    float e = expf(lg[idx] - m[d * NH + hh]);
    lg[idx] = e;
    atomicAdd(&dn[d * NH + hh], e);
}

// ---------------- edge pass 3: weighted scatter of messages ------------------
__global__ void scatter_kernel(const int* __restrict__ ei, const float* __restrict__ xh,
                               const float* __restrict__ ex, const float* __restrict__ dn,
                               float* __restrict__ out)
{
    int gw = (blockIdx.x * blockDim.x + threadIdx.x) >> 5;
    int lane = threadIdx.x & 31;
    if (gw >= NEA) return;
    int s, d;
    if (gw < NEDGE) { s = ei[gw]; d = ei[NEDGE + gw]; } else { s = d = gw - NEDGE; }
    float al[4];
#pragma unroll
    for (int h = 0; h < 4; h++) al[h] = ex[gw * 4 + h] / dn[d * 4 + h];
    const float* xr = xh + (size_t)s * HID;
    float* orow = out + (size_t)d * HID;
#pragma unroll
    for (int it = 0; it < 8; it++) {
        int c = it * 32 + lane;
        atomicAdd(&orow[c], xr[c] * al[it >> 1]);
    }
}

// ---------------- batchnorm ---------------------------------------------------
__global__ void bn_stats_kernel(const float* __restrict__ out, const float* __restrict__ gb,
                                float* __restrict__ bnsum)
{
    int t = threadIdx.x;
    int r0 = blockIdx.x * 512;
    int r1 = min(r0 + 512, NNODE);
    float gbv = gb[t];
    float s = 0.f, s2 = 0.f;
    for (int r = r0; r < r1; r++) {
        float v = out[(size_t)r * HID + t] + gbv;
        s += v; s2 += v * v;
    }
    atomicAdd(&bnsum[t], s);
    atomicAdd(&bnsum[HID + t], s2);
}

__global__ void bn_finalize_kernel(const float* __restrict__ bnsum,
                                   const float* __restrict__ gamma, const float* __restrict__ beta,
                                   float* __restrict__ ab)
{
    int t = threadIdx.x;
    if (t >= HID) return;
    float mu  = bnsum[t] / (float)NNODE;
    float var = bnsum[HID + t] / (float)NNODE - mu * mu;
    float a = gamma[t] * rsqrtf(var + EPSV);
    ab[t] = a;
    ab[HID + t] = beta[t] - mu * a;
}

__global__ void bn_apply_kernel(const float* __restrict__ out, const float* __restrict__ gb,
                                const float* __restrict__ ab, const float* __restrict__ hprev,
                                float* __restrict__ hnxt, int res)
{
    int idx = blockIdx.x * blockDim.x + threadIdx.x;   // grid = NNODE blocks of 256
    int c = threadIdx.x;
    float v = out[idx] + gb[c];
    v = v * ab[c] + ab[HID + c];
    v = fmaxf(v, 0.f);
    if (res) v += hprev[idx];
    hnxt[idx] = v;
}

// ---------------- pooling (batch_idx is sorted -> binary search ranges) ------
__global__ void pool_kernel(const float* __restrict__ h, const int* __restrict__ bidx,
                            float* __restrict__ g)
{
    int b = blockIdx.x;
    int t = threadIdx.x;
    __shared__ int slo, shi;
    if (t == 0) {
        int lo = 0, hi = NNODE;
        while (lo < hi) { int mid = (lo + hi) >> 1; if (bidx[mid] < b) lo = mid + 1; else hi = mid; }
        slo = lo;
        hi = NNODE;
        while (lo < hi) { int mid = (lo + hi) >> 1; if (bidx[mid] < b + 1) lo = mid + 1; else hi = mid; }
        shi = lo;
    }
    __syncthreads();
    int lo = slo, hi = shi;
    float s = 0.f;
    for (int r = lo; r < hi; r++) s += h[(size_t)r * HID + t];
    g[b * HID + t] = s / fmaxf((float)(hi - lo), 1.f);
}

// ---------------- final dot with p_W3 ----------------------------------------
__global__ void final_kernel(const float* __restrict__ z2, const float* __restrict__ w3,
                             const float* __restrict__ b3, float* __restrict__ outp)
{
    int gw = (blockIdx.x * blockDim.x + threadIdx.x) >> 5;
    int lane = threadIdx.x & 31;
    if (gw >= NB) return;
    float v = z2[gw * 64 + lane] * w3[lane] + z2[gw * 64 + lane + 32] * w3[lane + 32];
#pragma unroll
    for (int o = 16; o; o >>= 1) v += __shfl_xor_sync(0xFFFFFFFFu, v, o);
    if (lane == 0) outp[gw] = v + b3[0];
}

// ---------------- host orchestration -----------------------------------------
extern "C" void kernel_launch(void* const* d_in, const int* in_sizes, int n_in,
                              void* d_out, int out_size)
{
    // Input order follows the reference signature; batch_size may or may not be
    // materialized as an input array (it is a scalar). Handle both layouts.
    int o = (n_in >= 21) ? 0 : -1;
    const float* x      = (const float*)d_in[0];
    const int*   ei     = (const int*)  d_in[1];
    const float* eattr  = (const float*)d_in[2];
    const int*   bidx   = (const int*)  d_in[3];
    const float* in_W   = (const float*)d_in[5 + o];
    const float* in_b   = (const float*)d_in[6 + o];
    const float* gat_W  = (const float*)d_in[7 + o];
    const float* attS   = (const float*)d_in[8 + o];
    const float* attD   = (const float*)d_in[9 + o];
    const float* edge_W = (const float*)d_in[10 + o];
    const float* attE   = (const float*)d_in[11 + o];
    const float* gat_b  = (const float*)d_in[12 + o];
    const float* bn_g   = (const float*)d_in[13 + o];
    const float* bn_b   = (const float*)d_in[14 + o];
    const float* p_W1   = (const float*)d_in[15 + o];
    const float* p_b1   = (const float*)d_in[16 + o];
    const float* p_W2   = (const float*)d_in[17 + o];
    const float* p_b2   = (const float*)d_in[18 + o];
    const float* p_W3   = (const float*)d_in[19 + o];
    const float* p_b3   = (const float*)d_in[20 + o];
    float* outp = (float*)d_out;

    float *h0, *h1, *xh, *outb, *lattr, *deg, *as_, *ad_, *lg, *m_, *dn, *we,
          *bnsum, *bnab, *pool, *z1, *z2;
    cudaGetSymbolAddress((void**)&h0,    g_h0);
    cudaGetSymbolAddress((void**)&h1,    g_h1);
    cudaGetSymbolAddress((void**)&xh,    g_xh);
    cudaGetSymbolAddress((void**)&outb,  g_out);
    cudaGetSymbolAddress((void**)&lattr, g_lattr);
    cudaGetSymbolAddress((void**)&deg,   g_deg);
    cudaGetSymbolAddress((void**)&as_,   g_as);
    cudaGetSymbolAddress((void**)&ad_,   g_ad);
    cudaGetSymbolAddress((void**)&lg,    g_lg);
    cudaGetSymbolAddress((void**)&m_,    g_m);
    cudaGetSymbolAddress((void**)&dn,    g_dn);
    cudaGetSymbolAddress((void**)&we,    g_we);
    cudaGetSymbolAddress((void**)&bnsum, g_bnsum);
    cudaGetSymbolAddress((void**)&bnab,  g_bnab);
    cudaGetSymbolAddress((void**)&pool,  g_pool);
    cudaGetSymbolAddress((void**)&z1,    g_z1);
    cudaGetSymbolAddress((void**)&z2,    g_z2);

    // self-loop edge attributes (mean of incoming)
    cudaMemsetAsync(deg, 0, NNODE * sizeof(float));
    cudaMemsetAsync(lattr, 0, NNODE * DE * sizeof(float));
    edge_deg_kernel<<<(NEDGE + 255) / 256, 256>>>(ei, eattr, deg, lattr);
    loop_norm_kernel<<<(NNODE + 255) / 256, 256>>>(deg, lattr);

    // input projection: h0 = relu(x @ in_W + in_b)
    sgemm_kernel<<<dim3((HID + 127) / 128, (NNODE + 127) / 128), 256>>>(
        x, in_W, in_b, h0, NNODE, DIN, HID, 1);

    float* hcur = h0;
    float* hnxt = h1;
    for (int i = 0; i < NLAY; i++) {
        we_kernel<<<1, 32>>>(edge_W + (size_t)i * DE * HID, attE + i * NH * CC, we);
        sgemm_kernel<<<dim3((HID + 127) / 128, (NNODE + 127) / 128), 256>>>(
            hcur, gat_W + (size_t)i * HID * HID, nullptr, xh, NNODE, HID, HID, 0);
        attn_node_kernel<<<(NNODE * NH * 32 + 255) / 256, 256>>>(
            xh, attS + i * NH * CC, attD + i * NH * CC, as_, ad_);
        layer_reset_kernel<<<(NNODE * NH + 255) / 256, 256>>>(m_, dn, bnsum);
        edge_logits_kernel<<<(NEA * NH + 255) / 256, 256>>>(ei, eattr, lattr, we, as_, ad_, lg, m_);
        edge_exp_kernel<<<(NEA * NH + 255) / 256, 256>>>(ei, lg, m_, dn);
        cudaMemsetAsync(outb, 0, (size_t)NNODE * HID * sizeof(float));
        scatter_kernel<<<(NEA * 32 + 255) / 256, 256>>>(ei, xh, lg, dn, outb);
        bn_stats_kernel<<<(NNODE + 511) / 512, 256>>>(outb, gat_b + i * HID, bnsum);
        bn_finalize_kernel<<<1, 256>>>(bnsum, bn_g + i * HID, bn_b + i * HID, bnab);
        bn_apply_kernel<<<NNODE, 256>>>(outb, gat_b + i * HID, bnab, hcur, hnxt, i > 0 ? 1 : 0);
        float* t = hcur; hcur = hnxt; hnxt = t;
    }

    // global mean pool + predictor MLP
    pool_kernel<<<NB, 256>>>(hcur, bidx, pool);
    sgemm_kernel<<<dim3(1, (NB + 127) / 128), 256>>>(pool, p_W1, p_b1, z1, NB, HID, 128, 1);
    sgemm_kernel<<<dim3(1, (NB + 127) / 128), 256>>>(z1, p_W2, p_b2, z2, NB, 128, 64, 1);
    final_kernel<<<(NB * 32 + 255) / 256, 256>>>(z2, p_W3, p_b3, outp);
}

// round 2
// speedup vs baseline: 1.4617x; 1.4617x over previous
#include <cuda_runtime.h>
#include <math.h>
#include <stdint.h>

#define NNODE 150000
#define NEDGE 300000
#define NEA   450000   // NEDGE + NNODE (with self loops)
#define NB    4096
#define DIN   155
#define DE    6
#define HID   256
#define NH    4
#define CC    64
#define NLAY  4
#define NEGSL 0.2f
#define EPSV  1e-5f

// ---------------- scratch (static device globals; no allocation) -------------
__device__ float g_h0[NNODE*HID];
__device__ float g_h1[NNODE*HID];
__device__ float g_xh[NNODE*HID];
__device__ float g_out[NNODE*HID];
__device__ float g_lattr[NNODE*DE];
__device__ float g_deg[NNODE];
__device__ float g_as[NNODE*NH];
__device__ float g_ad[NNODE*NH];
__device__ float g_lg[NEA*NH];
__device__ float g_m[NNODE*NH];
__device__ float g_dn[NNODE*NH];
__device__ float g_we[DE*NH];
__device__ float g_bnsum[2*HID];
__device__ float g_bnab[2*HID];
__device__ float g_pool[NB*HID];
__device__ float g_z1[NB*128];
__device__ float g_z2[NB*64];

// ---------------- helpers ----------------------------------------------------
__device__ __forceinline__ void atomicMaxF(float* addr, float v) {
    if (v >= 0.f) atomicMax((int*)addr, __float_as_int(v));
    else          atomicMin((unsigned int*)addr, (unsigned int)__float_as_int(v));
}

__device__ __forceinline__ void cp_async16(uint32_t dst, const void* src, int bytes) {
    asm volatile("cp.async.cg.shared.global [%0], [%1], 16, %2;\n"
                 :: "r"(dst), "l"(src), "r"(bytes));
}
__device__ __forceinline__ unsigned cvt_tf32(float x) {
    unsigned r;
    asm("cvt.rna.tf32.f32 %0, %1;" : "=r"(r) : "f"(x));
    return r;
}
__device__ __forceinline__ void mma8(float c[4], const unsigned a[4], unsigned b0, unsigned b1) {
    asm volatile("mma.sync.aligned.m16n8k8.row.col.f32.tf32.tf32.f32 "
                 "{%0,%1,%2,%3},{%4,%5,%6,%7},{%8,%9},{%0,%1,%2,%3};\n"
                 : "+f"(c[0]), "+f"(c[1]), "+f"(c[2]), "+f"(c[3])
                 : "r"(a[0]), "r"(a[1]), "r"(a[2]), "r"(a[3]), "r"(b0), "r"(b1));
}

// ---------------- tf32 (3x-split) tensor-core GEMM ---------------------------
// C[M,N] = relu?(A[M,K] @ B[K,N] + bias); requires N % 128 == 0.
// Block 128x128, BK=32, 8 warps (warp tile 32x64), cp.async double buffer.
// Accuracy: 3xTF32 (hi*hi + hi*lo + lo*hi) ~ fp32.
#define G_ASTRIDE 36
#define G_BSTRIDE 136
#define G_ASZ (128*G_ASTRIDE)          // 4608 floats
#define G_BSZ (32*G_BSTRIDE)           // 4352 floats
#define G_BUF (G_ASZ + G_BSZ)          // 8960 floats
#define G_SMEM_BYTES (2*G_BUF*4)       // 71680 bytes

__global__ __launch_bounds__(256)
void gemm_tf32_kernel(const float* __restrict__ A, const float* __restrict__ B,
                      const float* __restrict__ bias, float* __restrict__ C,
                      int M, int K, int N, int doRelu)
{
    extern __shared__ float smg[];
    const int tid  = threadIdx.x;
    const int lane = tid & 31;
    const int wid  = tid >> 5;
    const int wm   = (wid & 3) * 32;
    const int wn   = (wid >> 2) * 64;
    const int bm   = blockIdx.y * 128;
    const int bn   = blockIdx.x * 128;
    const int alignedK = ((K & 3) == 0);

    float c[2][8][4];
#pragma unroll
    for (int mi = 0; mi < 2; mi++)
#pragma unroll
        for (int ni = 0; ni < 8; ni++)
#pragma unroll
            for (int q = 0; q < 4; q++) c[mi][ni][q] = 0.f;

    const int nkt = (K + 31) / 32;

    auto loadTile = [&](int kt, int buf) {
        float* Ab = smg + buf * G_BUF;
        float* Bb = Ab + G_ASZ;
        uint32_t abase = (uint32_t)__cvta_generic_to_shared(Ab);
        uint32_t bbase = (uint32_t)__cvta_generic_to_shared(Bb);
        const int ar = tid >> 3, ak = (tid & 7) * 4;
        const int gk = kt * 32 + ak;
        if (alignedK) {
#pragma unroll
            for (int i = 0; i < 4; i++) {
                int row = ar + i * 32;
                int grow = bm + row;
                int bytes = (grow < M) ? max(0, min(16, (K - gk) * 4)) : 0;
                const float* src = A + (size_t)(grow < M ? grow : 0) * K + (gk < K ? gk : 0);
                cp_async16(abase + (uint32_t)(row * G_ASTRIDE + ak) * 4u, src, bytes);
            }
        } else {
            // scalar path (K=155: rows not 16B aligned)
#pragma unroll
            for (int i = 0; i < 4; i++) {
                int row = ar + i * 32;
                int grow = bm + row;
#pragma unroll
                for (int j = 0; j < 4; j++) {
                    float v = 0.f;
                    if (grow < M && gk + j < K) v = A[(size_t)grow * K + gk + j];
                    Ab[row * G_ASTRIDE + ak + j] = v;
                }
            }
        }
        const int bc = (tid & 31) * 4;
        const int br = tid >> 5;
#pragma unroll
        for (int i = 0; i < 4; i++) {
            int row = br + i * 8;
            int gkr = kt * 32 + row;
            int bytes = (gkr < K) ? 16 : 0;
            const float* src = B + (size_t)(gkr < K ? gkr : 0) * N + bn + bc;
            cp_async16(bbase + (uint32_t)(row * G_BSTRIDE + bc) * 4u, src, bytes);
        }
    };

    auto computeTile = [&](int buf) {
        float* Ab = smg + buf * G_BUF;
        float* Bb = Ab + G_ASZ;
#pragma unroll
        for (int ks = 0; ks < 4; ks++) {
            unsigned ah[2][4], al[2][4];
            const int kk = ks * 8 + (lane & 3);
#pragma unroll
            for (int mi = 0; mi < 2; mi++) {
                int r0 = wm + mi * 16 + (lane >> 2);
#pragma unroll
                for (int q = 0; q < 4; q++) {
                    int rr = r0 + (q & 1) * 8;
                    int kc = kk + (q >> 1) * 4;
                    float v = Ab[rr * G_ASTRIDE + kc];
                    unsigned h = cvt_tf32(v);
                    ah[mi][q] = h;
                    al[mi][q] = cvt_tf32(v - __uint_as_float(h));
                }
            }
#pragma unroll
            for (int ni = 0; ni < 8; ni++) {
                int cc0 = wn + ni * 8 + (lane >> 2);
                float b0f = Bb[(ks * 8 + (lane & 3)) * G_BSTRIDE + cc0];
                float b1f = Bb[(ks * 8 + (lane & 3) + 4) * G_BSTRIDE + cc0];
                unsigned bh0 = cvt_tf32(b0f), bh1 = cvt_tf32(b1f);
                unsigned bl0 = cvt_tf32(b0f - __uint_as_float(bh0));
                unsigned bl1 = cvt_tf32(b1f - __uint_as_float(bh1));
#pragma unroll
                for (int mi = 0; mi < 2; mi++) {
                    mma8(c[mi][ni], ah[mi], bh0, bh1);
                    mma8(c[mi][ni], ah[mi], bl0, bl1);
                    mma8(c[mi][ni], al[mi], bh0, bh1);
                }
            }
        }
    };

    loadTile(0, 0);
    asm volatile("cp.async.commit_group;\n");
    for (int kt = 0; kt < nkt; kt++) {
        if (kt + 1 < nkt) {
            loadTile(kt + 1, (kt + 1) & 1);
            asm volatile("cp.async.commit_group;\n");
            asm volatile("cp.async.wait_group 1;\n");
        } else {
            asm volatile("cp.async.wait_group 0;\n");
        }
        __syncthreads();
        computeTile(kt & 1);
        __syncthreads();
    }

#pragma unroll
    for (int mi = 0; mi < 2; mi++) {
        int r0 = bm + wm + mi * 16 + (lane >> 2);
#pragma unroll
        for (int ni = 0; ni < 8; ni++) {
            int col = bn + wn + ni * 8 + (lane & 3) * 2;
            float bv0 = bias ? bias[col] : 0.f;
            float bv1 = bias ? bias[col + 1] : 0.f;
            float v0 = c[mi][ni][0] + bv0, v1 = c[mi][ni][1] + bv1;
            float v2 = c[mi][ni][2] + bv0, v3 = c[mi][ni][3] + bv1;
            if (doRelu) {
                v0 = fmaxf(v0, 0.f); v1 = fmaxf(v1, 0.f);
                v2 = fmaxf(v2, 0.f); v3 = fmaxf(v3, 0.f);
            }
            if (r0 < M)     *(float2*)&C[(size_t)r0 * N + col]       = make_float2(v0, v1);
            if (r0 + 8 < M) *(float2*)&C[(size_t)(r0 + 8) * N + col] = make_float2(v2, v3);
        }
    }
}

// ---------------- generic tiled SGEMM (small MLP matmuls) --------------------
__global__ __launch_bounds__(256)
void sgemm_kernel(const float* __restrict__ A, const float* __restrict__ B,
                  const float* __restrict__ bias, float* __restrict__ C,
                  int M, int K, int N, int doRelu)
{
    const int BM = 128, BN = 128, BK = 8;
    __shared__ float As[BK][BM + 4];
    __shared__ float Bs[BK][BN];
    int tid = threadIdx.x;
    int bm = blockIdx.y * BM, bn = blockIdx.x * BN;
    int ty = tid >> 4, tx = tid & 15;
    float acc[8][8];
#pragma unroll
    for (int i = 0; i < 8; i++)
#pragma unroll
        for (int j = 0; j < 8; j++) acc[i][j] = 0.f;

    for (int k0 = 0; k0 < K; k0 += BK) {
#pragma unroll
        for (int i = 0; i < 4; i++) {
            int l = tid + i * 256;
            int r = l >> 3, c = l & 7;
            int gr = bm + r, gc = k0 + c;
            As[c][r] = (gr < M && gc < K) ? A[(size_t)gr * K + gc] : 0.f;
        }
#pragma unroll
        for (int i = 0; i < 4; i++) {
            int l = tid + i * 256;
            int r = l >> 7, c = l & 127;
            int gr = k0 + r, gc = bn + c;
            Bs[r][c] = (gr < K && gc < N) ? B[(size_t)gr * N + gc] : 0.f;
        }
        __syncthreads();
#pragma unroll
        for (int k = 0; k < BK; k++) {
            float4 av0 = *(const float4*)&As[k][ty * 8];
            float4 av1 = *(const float4*)&As[k][ty * 8 + 4];
            float4 bv0 = *(const float4*)&Bs[k][tx * 8];
            float4 bv1 = *(const float4*)&Bs[k][tx * 8 + 4];
            float ar[8] = {av0.x, av0.y, av0.z, av0.w, av1.x, av1.y, av1.z, av1.w};
            float br[8] = {bv0.x, bv0.y, bv0.z, bv0.w, bv1.x, bv1.y, bv1.z, bv1.w};
#pragma unroll
            for (int i = 0; i < 8; i++)
#pragma unroll
                for (int j = 0; j < 8; j++) acc[i][j] += ar[i] * br[j];
        }
        __syncthreads();
    }
#pragma unroll
    for (int i = 0; i < 8; i++) {
        int gr = bm + ty * 8 + i;
        if (gr >= M) continue;
#pragma unroll
        for (int j = 0; j < 8; j++) {
            int gc = bn + tx * 8 + j;
            if (gc >= N) continue;
            float v = acc[i][j];
            if (bias) v += bias[gc];
            if (doRelu) v = fmaxf(v, 0.f);
            C[(size_t)gr * N + gc] = v;
        }
    }
}

// ---------------- self-loop attr (mean of incoming edge feats) ---------------
__global__ void edge_deg_kernel(const int* __restrict__ ei, const float* __restrict__ eattr,
                                float* __restrict__ deg, float* __restrict__ lattr)
{
    int e = blockIdx.x * blockDim.x + threadIdx.x;
    if (e >= NEDGE) return;
    int d = ei[NEDGE + e];
    atomicAdd(&deg[d], 1.f);
#pragma unroll
    for (int k = 0; k < DE; k++) atomicAdd(&lattr[d * DE + k], eattr[e * DE + k]);
}

__global__ void loop_norm_kernel(const float* __restrict__ deg, float* __restrict__ lattr)
{
    int n = blockIdx.x * blockDim.x + threadIdx.x;
    if (n >= NNODE) return;
    float inv = 1.f / fmaxf(deg[n], 1.f);
#pragma unroll
    for (int k = 0; k < DE; k++) lattr[n * DE + k] *= inv;
}

// ---------------- per-layer: contracted edge attention weights ---------------
__global__ void we_kernel(const float* __restrict__ eW, const float* __restrict__ aE,
                          float* __restrict__ we)
{
    int t = threadIdx.x;
    if (t >= DE * NH) return;
    int k = t >> 2, hh = t & 3;
    float s = 0.f;
    for (int c = 0; c < CC; c++) s += eW[k * HID + hh * CC + c] * aE[hh * CC + c];
    we[t] = s;
}

// ---------------- node attention scalars a_s, a_d ----------------------------
__global__ void attn_node_kernel(const float* __restrict__ xh, const float* __restrict__ wsrc,
                                 const float* __restrict__ wdst,
                                 float* __restrict__ a_s, float* __restrict__ a_d)
{
    int gw = (blockIdx.x * blockDim.x + threadIdx.x) >> 5;
    int lane = threadIdx.x & 31;
    if (gw >= NNODE * NH) return;
    int n = gw >> 2, hh = gw & 3;
    const float* row = xh + (size_t)n * HID + hh * CC;
    const float* ws = wsrc + hh * CC;
    const float* wd = wdst + hh * CC;
    float v0 = row[lane], v1 = row[lane + 32];
    float s = v0 * ws[lane] + v1 * ws[lane + 32];
    float d = v0 * wd[lane] + v1 * wd[lane + 32];
#pragma unroll
    for (int o = 16; o; o >>= 1) {
        s += __shfl_xor_sync(0xFFFFFFFFu, s, o);
        d += __shfl_xor_sync(0xFFFFFFFFu, d, o);
    }
    if (lane == 0) { a_s[gw] = s; a_d[gw] = d; }
}

// ---------------- reset m / denom / bn sums ----------------------------------
__global__ void layer_reset_kernel(float* __restrict__ m, float* __restrict__ dn,
                                   float* __restrict__ bnsum)
{
    int idx = blockIdx.x * blockDim.x + threadIdx.x;
    if (idx < NNODE * NH) { m[idx] = -INFINITY; dn[idx] = 0.f; }
    if (idx < 2 * HID) bnsum[idx] = 0.f;
}

// ---------------- edge pass 1: logits + segment max --------------------------
__global__ void edge_logits_kernel(const int* __restrict__ ei, const float* __restrict__ eattr,
                                   const float* __restrict__ lattr, const float* __restrict__ we,
                                   const float* __restrict__ a_s, const float* __restrict__ a_d,
                                   float* __restrict__ lg, float* __restrict__ m)
{
    int idx = blockIdx.x * blockDim.x + threadIdx.x;
    if (idx >= NEA * NH) return;
    int ea = idx >> 2, hh = idx & 3;
    int s, d; const float* at;
    if (ea < NEDGE) { s = ei[ea]; d = ei[NEDGE + ea]; at = eattr + (size_t)ea * DE; }
    else            { s = d = ea - NEDGE;             at = lattr + (size_t)(ea - NEDGE) * DE; }
    float ae = 0.f;
#pragma unroll
    for (int k = 0; k < DE; k++) ae += at[k] * we[k * NH + hh];
    float v = a_s[s * NH + hh] + a_d[d * NH + hh] + ae;
    v = v > 0.f ? v : NEGSL * v;
    lg[idx] = v;
    atomicMaxF(&m[d * NH + hh], v);
}

// ---------------- edge pass 2: exp + segment sum -----------------------------
__global__ void edge_exp_kernel(const int* __restrict__ ei, float* __restrict__ lg,
                                const float* __restrict__ m, float* __restrict__ dn)
{
    int idx = blockIdx.x * blockDim.x + threadIdx.x;
    if (idx >= NEA * NH) return;
    int ea = idx >> 2, hh = idx & 3;
    int d = (ea < NEDGE) ? ei[NEDGE + ea] : (ea - NEDGE);
    float e = expf(lg[idx] - m[d * NH + hh]);
    lg[idx] = e;
    atomicAdd(&dn[d * NH + hh], e);
}

// ---------------- edge pass 3: weighted scatter of messages ------------------
__global__ void scatter_kernel(const int* __restrict__ ei, const float* __restrict__ xh,
                               const float* __restrict__ ex, const float* __restrict__ dn,
                               float* __restrict__ out)
{
    int gw = (blockIdx.x * blockDim.x + threadIdx.x) >> 5;
    int lane = threadIdx.x & 31;
    if (gw >= NEA) return;
    int s, d;
    if (gw < NEDGE) { s = ei[gw]; d = ei[NEDGE + gw]; } else { s = d = gw - NEDGE; }
    float al[4];
#pragma unroll
    for (int h = 0; h < 4; h++) al[h] = ex[gw * 4 + h] / dn[d * 4 + h];
    const float4* xr4 = (const float4*)(xh + (size_t)s * HID);
    float* orow = out + (size_t)d * HID;
#pragma unroll
    for (int it = 0; it < 2; it++) {
        int q = it * 32 + lane;            // float4 index, cols 4q..4q+3
        float a = al[q >> 4];              // head = (4q)/64 = q/16
        float4 v = xr4[q];
        atomicAdd(&orow[4 * q + 0], v.x * a);
        atomicAdd(&orow[4 * q + 1], v.y * a);
        atomicAdd(&orow[4 * q + 2], v.z * a);
        atomicAdd(&orow[4 * q + 3], v.w * a);
    }
}

// ---------------- batchnorm ---------------------------------------------------
__global__ void bn_stats_kernel(const float* __restrict__ out, const float* __restrict__ gb,
                                float* __restrict__ bnsum)
{
    int t = threadIdx.x;
    int r0 = blockIdx.x * 512;
    int r1 = min(r0 + 512, NNODE);
    float gbv = gb[t];
    float s = 0.f, s2 = 0.f;
    for (int r = r0; r < r1; r++) {
        float v = out[(size_t)r * HID + t] + gbv;
        s += v; s2 += v * v;
    }
    atomicAdd(&bnsum[t], s);
    atomicAdd(&bnsum[HID + t], s2);
}

__global__ void bn_finalize_kernel(const float* __restrict__ bnsum,
                                   const float* __restrict__ gamma, const float* __restrict__ beta,
                                   float* __restrict__ ab)
{
    int t = threadIdx.x;
    if (t >= HID) return;
    float mu  = bnsum[t] / (float)NNODE;
    float var = bnsum[HID + t] / (float)NNODE - mu * mu;
    float a = gamma[t] * rsqrtf(var + EPSV);
    ab[t] = a;
    ab[HID + t] = beta[t] - mu * a;
}

__global__ void bn_apply_kernel(const float* __restrict__ out, const float* __restrict__ gb,
                                const float* __restrict__ ab, const float* __restrict__ hprev,
                                float* __restrict__ hnxt, int res)
{
    int idx = blockIdx.x * blockDim.x + threadIdx.x;   // grid = NNODE blocks of 256
    int c = threadIdx.x;
    float v = out[idx] + gb[c];
    v = v * ab[c] + ab[HID + c];
    v = fmaxf(v, 0.f);
    if (res) v += hprev[idx];
    hnxt[idx] = v;
}

// ---------------- pooling (batch_idx is sorted -> binary search ranges) ------
__global__ void pool_kernel(const float* __restrict__ h, const int* __restrict__ bidx,
                            float* __restrict__ g)
{
    int b = blockIdx.x;
    int t = threadIdx.x;
    __shared__ int slo, shi;
    if (t == 0) {
        int lo = 0, hi = NNODE;
        while (lo < hi) { int mid = (lo + hi) >> 1; if (bidx[mid] < b) lo = mid + 1; else hi = mid; }
        slo = lo;
        hi = NNODE;
        while (lo < hi) { int mid = (lo + hi) >> 1; if (bidx[mid] < b + 1) lo = mid + 1; else hi = mid; }
        shi = lo;
    }
    __syncthreads();
    int lo = slo, hi = shi;
    float s = 0.f;
    for (int r = lo; r < hi; r++) s += h[(size_t)r * HID + t];
    g[b * HID + t] = s / fmaxf((float)(hi - lo), 1.f);
}

// ---------------- final dot with p_W3 ----------------------------------------
__global__ void final_kernel(const float* __restrict__ z2, const float* __restrict__ w3,
                             const float* __restrict__ b3, float* __restrict__ outp)
{
    int gw = (blockIdx.x * blockDim.x + threadIdx.x) >> 5;
    int lane = threadIdx.x & 31;
    if (gw >= NB) return;
    float v = z2[gw * 64 + lane] * w3[lane] + z2[gw * 64 + lane + 32] * w3[lane + 32];
#pragma unroll
    for (int o = 16; o; o >>= 1) v += __shfl_xor_sync(0xFFFFFFFFu, v, o);
    if (lane == 0) outp[gw] = v + b3[0];
}

// ---------------- host orchestration -----------------------------------------
extern "C" void kernel_launch(void* const* d_in, const int* in_sizes, int n_in,
                              void* d_out, int out_size)
{
    int o = (n_in >= 21) ? 0 : -1;
    const float* x      = (const float*)d_in[0];
    const int*   ei     = (const int*)  d_in[1];
    const float* eattr  = (const float*)d_in[2];
    const int*   bidx   = (const int*)  d_in[3];
    const float* in_W   = (const float*)d_in[5 + o];
    const float* in_b   = (const float*)d_in[6 + o];
    const float* gat_W  = (const float*)d_in[7 + o];
    const float* attS   = (const float*)d_in[8 + o];
    const float* attD   = (const float*)d_in[9 + o];
    const float* edge_W = (const float*)d_in[10 + o];
    const float* attE   = (const float*)d_in[11 + o];
    const float* gat_b  = (const float*)d_in[12 + o];
    const float* bn_g   = (const float*)d_in[13 + o];
    const float* bn_b   = (const float*)d_in[14 + o];
    const float* p_W1   = (const float*)d_in[15 + o];
    const float* p_b1   = (const float*)d_in[16 + o];
    const float* p_W2   = (const float*)d_in[17 + o];
    const float* p_b2   = (const float*)d_in[18 + o];
    const float* p_W3   = (const float*)d_in[19 + o];
    const float* p_b3   = (const float*)d_in[20 + o];
    float* outp = (float*)d_out;

    float *h0, *h1, *xh, *outb, *lattr, *deg, *as_, *ad_, *lg, *m_, *dn, *we,
          *bnsum, *bnab, *pool, *z1, *z2;
    cudaGetSymbolAddress((void**)&h0,    g_h0);
    cudaGetSymbolAddress((void**)&h1,    g_h1);
    cudaGetSymbolAddress((void**)&xh,    g_xh);
    cudaGetSymbolAddress((void**)&outb,  g_out);
    cudaGetSymbolAddress((void**)&lattr, g_lattr);
    cudaGetSymbolAddress((void**)&deg,   g_deg);
    cudaGetSymbolAddress((void**)&as_,   g_as);
    cudaGetSymbolAddress((void**)&ad_,   g_ad);
    cudaGetSymbolAddress((void**)&lg,    g_lg);
    cudaGetSymbolAddress((void**)&m_,    g_m);
    cudaGetSymbolAddress((void**)&dn,    g_dn);
    cudaGetSymbolAddress((void**)&we,    g_we);
    cudaGetSymbolAddress((void**)&bnsum, g_bnsum);
    cudaGetSymbolAddress((void**)&bnab,  g_bnab);
    cudaGetSymbolAddress((void**)&pool,  g_pool);
    cudaGetSymbolAddress((void**)&z1,    g_z1);
    cudaGetSymbolAddress((void**)&z2,    g_z2);

    cudaFuncSetAttribute(gemm_tf32_kernel,
                         cudaFuncAttributeMaxDynamicSharedMemorySize, G_SMEM_BYTES);

    // self-loop edge attributes (mean of incoming)
    cudaMemsetAsync(deg, 0, NNODE * sizeof(float));
    cudaMemsetAsync(lattr, 0, NNODE * DE * sizeof(float));
    edge_deg_kernel<<<(NEDGE + 255) / 256, 256>>>(ei, eattr, deg, lattr);
    loop_norm_kernel<<<(NNODE + 255) / 256, 256>>>(deg, lattr);

    // input projection: h0 = relu(x @ in_W + in_b)   [tf32 tensor cores]
    gemm_tf32_kernel<<<dim3(HID / 128, (NNODE + 127) / 128), 256, G_SMEM_BYTES>>>(
        x, in_W, in_b, h0, NNODE, DIN, HID, 1);

    float* hcur = h0;
    float* hnxt = h1;
    for (int i = 0; i < NLAY; i++) {
        we_kernel<<<1, 32>>>(edge_W + (size_t)i * DE * HID, attE + i * NH * CC, we);
        gemm_tf32_kernel<<<dim3(HID / 128, (NNODE + 127) / 128), 256, G_SMEM_BYTES>>>(
            hcur, gat_W + (size_t)i * HID * HID, nullptr, xh, NNODE, HID, HID, 0);
        attn_node_kernel<<<(NNODE * NH * 32 + 255) / 256, 256>>>(
            xh, attS + i * NH * CC, attD + i * NH * CC, as_, ad_);
        layer_reset_kernel<<<(NNODE * NH + 255) / 256, 256>>>(m_, dn, bnsum);
        edge_logits_kernel<<<(NEA * NH + 255) / 256, 256>>>(ei, eattr, lattr, we, as_, ad_, lg, m_);
        edge_exp_kernel<<<(NEA * NH + 255) / 256, 256>>>(ei, lg, m_, dn);
        cudaMemsetAsync(outb, 0, (size_t)NNODE * HID * sizeof(float));
        scatter_kernel<<<(NEA * 32 + 255) / 256, 256>>>(ei, xh, lg, dn, outb);
        bn_stats_kernel<<<(NNODE + 511) / 512, 256>>>(outb, gat_b + i * HID, bnsum);
        bn_finalize_kernel<<<1, 256>>>(bnsum, bn_g + i * HID, bn_b + i * HID, bnab);
        bn_apply_kernel<<<NNODE, 256>>>(outb, gat_b + i * HID, bnab, hcur, hnxt, i > 0 ? 1 : 0);
        float* t = hcur; hcur = hnxt; hnxt = t;
    }

    // global mean pool + predictor MLP
    pool_kernel<<<NB, 256>>>(hcur, bidx, pool);
    sgemm_kernel<<<dim3(1, (NB + 127) / 128), 256>>>(pool, p_W1, p_b1, z1, NB, HID, 128, 1);
    sgemm_kernel<<<dim3(1, (NB + 127) / 128), 256>>>(z1, p_W2, p_b2, z2, NB, 128, 64, 1);
    final_kernel<<<(NB * 32 + 255) / 256, 256>>>(z2, p_W3, p_b3, outp);
}

// round 3
// speedup vs baseline: 1.7426x; 1.1921x over previous
#include <cuda_runtime.h>
#include <math.h>
#include <stdint.h>

#define NNODE 150000
#define NEDGE 300000
#define NB    4096
#define DIN   155
#define DE    6
#define HID   256
#define NH    4
#define CC    64
#define NLAY  4
#define NEGSL 0.2f
#define EPSV  1e-5f
#define NSCAN_BLK ((NNODE + 255) / 256)   // 586

// ---------------- scratch (static device globals; no allocation) -------------
__device__ float g_h0[NNODE*HID];
__device__ float g_h1[NNODE*HID];
__device__ float g_xh[NNODE*HID];
__device__ float g_out[NNODE*HID];
__device__ float g_lattr[NNODE*DE];
__device__ float g_deg[NNODE];
__device__ float g_as[NNODE*NH];
__device__ float g_ad[NNODE*NH];
__device__ float g_we[DE*NH];
__device__ float g_bnsum[2*HID];
__device__ float g_bnab[2*HID];
__device__ float g_pool[NB*HID];
__device__ float g_z1[NB*128];
__device__ float g_z2[NB*64];
// CSR
__device__ int  g_indeg[NNODE];
__device__ int  g_off[NNODE + 1];
__device__ int  g_cursor[NNODE];
__device__ int  g_bsum[1024];
__device__ int2 g_csr[NEDGE];

// ---------------- helpers ----------------------------------------------------
__device__ __forceinline__ void cp_async16(uint32_t dst, const void* src, int bytes) {
    asm volatile("cp.async.cg.shared.global [%0], [%1], 16, %2;\n"
                 :: "r"(dst), "l"(src), "r"(bytes));
}
__device__ __forceinline__ unsigned cvt_tf32(float x) {
    unsigned r;
    asm("cvt.rna.tf32.f32 %0, %1;" : "=r"(r) : "f"(x));
    return r;
}
__device__ __forceinline__ void mma8(float c[4], const unsigned a[4], unsigned b0, unsigned b1) {
    asm volatile("mma.sync.aligned.m16n8k8.row.col.f32.tf32.tf32.f32 "
                 "{%0,%1,%2,%3},{%4,%5,%6,%7},{%8,%9},{%0,%1,%2,%3};\n"
                 : "+f"(c[0]), "+f"(c[1]), "+f"(c[2]), "+f"(c[3])
                 : "r"(a[0]), "r"(a[1]), "r"(a[2]), "r"(a[3]), "r"(b0), "r"(b1));
}

// ---------------- tf32 (3x-split) tensor-core GEMM ---------------------------
#define G_ASTRIDE 36
#define G_BSTRIDE 136
#define G_ASZ (128*G_ASTRIDE)
#define G_BSZ (32*G_BSTRIDE)
#define G_BUF (G_ASZ + G_BSZ)
#define G_SMEM_BYTES (2*G_BUF*4)

__global__ __launch_bounds__(256)
void gemm_tf32_kernel(const float* __restrict__ A, const float* __restrict__ B,
                      const float* __restrict__ bias, float* __restrict__ C,
                      int M, int K, int N, int doRelu)
{
    extern __shared__ float smg[];
    const int tid  = threadIdx.x;
    const int lane = tid & 31;
    const int wid  = tid >> 5;
    const int wm   = (wid & 3) * 32;
    const int wn   = (wid >> 2) * 64;
    const int bm   = blockIdx.y * 128;
    const int bn   = blockIdx.x * 128;
    const int alignedK = ((K & 3) == 0);

    float c[2][8][4];
#pragma unroll
    for (int mi = 0; mi < 2; mi++)
#pragma unroll
        for (int ni = 0; ni < 8; ni++)
#pragma unroll
            for (int q = 0; q < 4; q++) c[mi][ni][q] = 0.f;

    const int nkt = (K + 31) / 32;

    auto loadTile = [&](int kt, int buf) {
        float* Ab = smg + buf * G_BUF;
        float* Bb = Ab + G_ASZ;
        uint32_t abase = (uint32_t)__cvta_generic_to_shared(Ab);
        uint32_t bbase = (uint32_t)__cvta_generic_to_shared(Bb);
        const int ar = tid >> 3, ak = (tid & 7) * 4;
        const int gk = kt * 32 + ak;
        if (alignedK) {
#pragma unroll
            for (int i = 0; i < 4; i++) {
                int row = ar + i * 32;
                int grow = bm + row;
                int bytes = (grow < M) ? max(0, min(16, (K - gk) * 4)) : 0;
                const float* src = A + (size_t)(grow < M ? grow : 0) * K + (gk < K ? gk : 0);
                cp_async16(abase + (uint32_t)(row * G_ASTRIDE + ak) * 4u, src, bytes);
            }
        } else {
#pragma unroll
            for (int i = 0; i < 4; i++) {
                int row = ar + i * 32;
                int grow = bm + row;
#pragma unroll
                for (int j = 0; j < 4; j++) {
                    float v = 0.f;
                    if (grow < M && gk + j < K) v = A[(size_t)grow * K + gk + j];
                    Ab[row * G_ASTRIDE + ak + j] = v;
                }
            }
        }
        const int bc = (tid & 31) * 4;
        const int br = tid >> 5;
#pragma unroll
        for (int i = 0; i < 4; i++) {
            int row = br + i * 8;
            int gkr = kt * 32 + row;
            int bytes = (gkr < K) ? 16 : 0;
            const float* src = B + (size_t)(gkr < K ? gkr : 0) * N + bn + bc;
            cp_async16(bbase + (uint32_t)(row * G_BSTRIDE + bc) * 4u, src, bytes);
        }
    };

    auto computeTile = [&](int buf) {
        float* Ab = smg + buf * G_BUF;
        float* Bb = Ab + G_ASZ;
#pragma unroll
        for (int ks = 0; ks < 4; ks++) {
            unsigned ah[2][4], al[2][4];
            const int kk = ks * 8 + (lane & 3);
#pragma unroll
            for (int mi = 0; mi < 2; mi++) {
                int r0 = wm + mi * 16 + (lane >> 2);
#pragma unroll
                for (int q = 0; q < 4; q++) {
                    int rr = r0 + (q & 1) * 8;
                    int kc = kk + (q >> 1) * 4;
                    float v = Ab[rr * G_ASTRIDE + kc];
                    unsigned h = cvt_tf32(v);
                    ah[mi][q] = h;
                    al[mi][q] = cvt_tf32(v - __uint_as_float(h));
                }
            }
#pragma unroll
            for (int ni = 0; ni < 8; ni++) {
                int cc0 = wn + ni * 8 + (lane >> 2);
                float b0f = Bb[(ks * 8 + (lane & 3)) * G_BSTRIDE + cc0];
                float b1f = Bb[(ks * 8 + (lane & 3) + 4) * G_BSTRIDE + cc0];
                unsigned bh0 = cvt_tf32(b0f), bh1 = cvt_tf32(b1f);
                unsigned bl0 = cvt_tf32(b0f - __uint_as_float(bh0));
                unsigned bl1 = cvt_tf32(b1f - __uint_as_float(bh1));
#pragma unroll
                for (int mi = 0; mi < 2; mi++) {
                    mma8(c[mi][ni], ah[mi], bh0, bh1);
                    mma8(c[mi][ni], ah[mi], bl0, bl1);
                    mma8(c[mi][ni], al[mi], bh0, bh1);
                }
            }
        }
    };

    loadTile(0, 0);
    asm volatile("cp.async.commit_group;\n");
    for (int kt = 0; kt < nkt; kt++) {
        if (kt + 1 < nkt) {
            loadTile(kt + 1, (kt + 1) & 1);
            asm volatile("cp.async.commit_group;\n");
            asm volatile("cp.async.wait_group 1;\n");
        } else {
            asm volatile("cp.async.wait_group 0;\n");
        }
        __syncthreads();
        computeTile(kt & 1);
        __syncthreads();
    }

#pragma unroll
    for (int mi = 0; mi < 2; mi++) {
        int r0 = bm + wm + mi * 16 + (lane >> 2);
#pragma unroll
        for (int ni = 0; ni < 8; ni++) {
            int col = bn + wn + ni * 8 + (lane & 3) * 2;
            float bv0 = bias ? bias[col] : 0.f;
            float bv1 = bias ? bias[col + 1] : 0.f;
            float v0 = c[mi][ni][0] + bv0, v1 = c[mi][ni][1] + bv1;
            float v2 = c[mi][ni][2] + bv0, v3 = c[mi][ni][3] + bv1;
            if (doRelu) {
                v0 = fmaxf(v0, 0.f); v1 = fmaxf(v1, 0.f);
                v2 = fmaxf(v2, 0.f); v3 = fmaxf(v3, 0.f);
            }
            if (r0 < M)     *(float2*)&C[(size_t)r0 * N + col]       = make_float2(v0, v1);
            if (r0 + 8 < M) *(float2*)&C[(size_t)(r0 + 8) * N + col] = make_float2(v2, v3);
        }
    }
}

// ---------------- generic tiled SGEMM (small MLP matmuls) --------------------
__global__ __launch_bounds__(256)
void sgemm_kernel(const float* __restrict__ A, const float* __restrict__ B,
                  const float* __restrict__ bias, float* __restrict__ C,
                  int M, int K, int N, int doRelu)
{
    const int BM = 128, BN = 128, BK = 8;
    __shared__ float As[BK][BM + 4];
    __shared__ float Bs[BK][BN];
    int tid = threadIdx.x;
    int bm = blockIdx.y * BM, bn = blockIdx.x * BN;
    int ty = tid >> 4, tx = tid & 15;
    float acc[8][8];
#pragma unroll
    for (int i = 0; i < 8; i++)
#pragma unroll
        for (int j = 0; j < 8; j++) acc[i][j] = 0.f;

    for (int k0 = 0; k0 < K; k0 += BK) {
#pragma unroll
        for (int i = 0; i < 4; i++) {
            int l = tid + i * 256;
            int r = l >> 3, c = l & 7;
            int gr = bm + r, gc = k0 + c;
            As[c][r] = (gr < M && gc < K) ? A[(size_t)gr * K + gc] : 0.f;
        }
#pragma unroll
        for (int i = 0; i < 4; i++) {
            int l = tid + i * 256;
            int r = l >> 7, c = l & 127;
            int gr = k0 + r, gc = bn + c;
            Bs[r][c] = (gr < K && gc < N) ? B[(size_t)gr * N + gc] : 0.f;
        }
        __syncthreads();
#pragma unroll
        for (int k = 0; k < BK; k++) {
            float4 av0 = *(const float4*)&As[k][ty * 8];
            float4 av1 = *(const float4*)&As[k][ty * 8 + 4];
            float4 bv0 = *(const float4*)&Bs[k][tx * 8];
            float4 bv1 = *(const float4*)&Bs[k][tx * 8 + 4];
            float ar[8] = {av0.x, av0.y, av0.z, av0.w, av1.x, av1.y, av1.z, av1.w};
            float br[8] = {bv0.x, bv0.y, bv0.z, bv0.w, bv1.x, bv1.y, bv1.z, bv1.w};
#pragma unroll
            for (int i = 0; i < 8; i++)
#pragma unroll
                for (int j = 0; j < 8; j++) acc[i][j] += ar[i] * br[j];
        }
        __syncthreads();
    }
#pragma unroll
    for (int i = 0; i < 8; i++) {
        int gr = bm + ty * 8 + i;
        if (gr >= M) continue;
#pragma unroll
        for (int j = 0; j < 8; j++) {
            int gc = bn + tx * 8 + j;
            if (gc >= N) continue;
            float v = acc[i][j];
            if (bias) v += bias[gc];
            if (doRelu) v = fmaxf(v, 0.f);
            C[(size_t)gr * N + gc] = v;
        }
    }
}

// ---------------- self-loop attr + in-degree count ---------------------------
__global__ void edge_deg_kernel(const int* __restrict__ ei, const float* __restrict__ eattr,
                                float* __restrict__ deg, float* __restrict__ lattr,
                                int* __restrict__ indeg)
{
    int e = blockIdx.x * blockDim.x + threadIdx.x;
    if (e >= NEDGE) return;
    int d = ei[NEDGE + e];
    atomicAdd(&deg[d], 1.f);
    atomicAdd(&indeg[d], 1);
#pragma unroll
    for (int k = 0; k < DE; k++) atomicAdd(&lattr[d * DE + k], eattr[e * DE + k]);
}

__global__ void loop_norm_kernel(const float* __restrict__ deg, float* __restrict__ lattr)
{
    int n = blockIdx.x * blockDim.x + threadIdx.x;
    if (n >= NNODE) return;
    float inv = 1.f / fmaxf(deg[n], 1.f);
#pragma unroll
    for (int k = 0; k < DE; k++) lattr[n * DE + k] *= inv;
}

// ---------------- CSR build: scan + fill -------------------------------------
__global__ void scan_block_reduce(const int* __restrict__ cnt, int* __restrict__ bsum)
{
    __shared__ int s[256];
    int i = blockIdx.x * 256 + threadIdx.x;
    s[threadIdx.x] = (i < NNODE) ? cnt[i] : 0;
    __syncthreads();
    for (int o = 128; o; o >>= 1) {
        if (threadIdx.x < o) s[threadIdx.x] += s[threadIdx.x + o];
        __syncthreads();
    }
    if (threadIdx.x == 0) bsum[blockIdx.x] = s[0];
}

__global__ void scan_bsum_kernel(int* __restrict__ bsum)
{
    __shared__ int s[1024];
    int t = threadIdx.x;
    int v = (t < NSCAN_BLK) ? bsum[t] : 0;
    s[t] = v;
    for (int o = 1; o < 1024; o <<= 1) {
        __syncthreads();
        int u = (t >= o) ? s[t - o] : 0;
        __syncthreads();
        s[t] += u;
    }
    if (t < NSCAN_BLK) bsum[t] = s[t] - v;   // exclusive
}

__global__ void scan_offsets_kernel(const int* __restrict__ cnt, const int* __restrict__ bsum,
                                    int* __restrict__ off, int* __restrict__ cursor)
{
    __shared__ int s[256];
    int i = blockIdx.x * 256 + threadIdx.x;
    int v = (i < NNODE) ? cnt[i] : 0;
    s[threadIdx.x] = v;
    for (int o = 1; o < 256; o <<= 1) {
        __syncthreads();
        int u = (threadIdx.x >= o) ? s[threadIdx.x - o] : 0;
        __syncthreads();
        s[threadIdx.x] += u;
    }
    __syncthreads();
    int excl = s[threadIdx.x] - v + bsum[blockIdx.x];
    if (i < NNODE) { off[i] = excl; cursor[i] = excl; }
    if (i == NNODE - 1) off[NNODE] = excl + v;
}

__global__ void csr_fill_kernel(const int* __restrict__ ei, int* __restrict__ cursor,
                                int2* __restrict__ csr)
{
    int e = blockIdx.x * blockDim.x + threadIdx.x;
    if (e >= NEDGE) return;
    int d = ei[NEDGE + e];
    int pos = atomicAdd(&cursor[d], 1);
    csr[pos] = make_int2(ei[e], e);
}

// ---------------- per-layer: contracted edge attention weights ---------------
__global__ void we_kernel(const float* __restrict__ eW, const float* __restrict__ aE,
                          float* __restrict__ we)
{
    int t = threadIdx.x;
    if (t >= DE * NH) return;
    int k = t >> 2, hh = t & 3;
    float s = 0.f;
    for (int c = 0; c < CC; c++) s += eW[k * HID + hh * CC + c] * aE[hh * CC + c];
    we[t] = s;
}

// ---------------- node attention scalars a_s, a_d ----------------------------
__global__ void attn_node_kernel(const float* __restrict__ xh, const float* __restrict__ wsrc,
                                 const float* __restrict__ wdst,
                                 float* __restrict__ a_s, float* __restrict__ a_d)
{
    int gw = (blockIdx.x * blockDim.x + threadIdx.x) >> 5;
    int lane = threadIdx.x & 31;
    if (gw >= NNODE * NH) return;
    int n = gw >> 2, hh = gw & 3;
    const float* row = xh + (size_t)n * HID + hh * CC;
    const float* ws = wsrc + hh * CC;
    const float* wd = wdst + hh * CC;
    float v0 = row[lane], v1 = row[lane + 32];
    float s = v0 * ws[lane] + v1 * ws[lane + 32];
    float d = v0 * wd[lane] + v1 * wd[lane + 32];
#pragma unroll
    for (int o = 16; o; o >>= 1) {
        s += __shfl_xor_sync(0xFFFFFFFFu, s, o);
        d += __shfl_xor_sync(0xFFFFFFFFu, d, o);
    }
    if (lane == 0) { a_s[gw] = s; a_d[gw] = d; }
}

// ---------------- fused GAT softmax + aggregate (warp per dst node) ----------
__global__ __launch_bounds__(256)
void gat_aggregate_kernel(const int2* __restrict__ csr, const int* __restrict__ off,
                          const float* __restrict__ eattr, const float* __restrict__ lattr,
                          const float* __restrict__ we,
                          const float* __restrict__ a_s, const float* __restrict__ a_d,
                          const float* __restrict__ xh, float* __restrict__ out)
{
    int gw = (blockIdx.x * blockDim.x + threadIdx.x) >> 5;
    int lane = threadIdx.x & 31;
    if (gw >= NNODE) return;
    const int n = gw;
    const int lo = off[n], hi = off[n + 1];
    const int myh = lane >> 3;

    float w[DE * NH];
#pragma unroll
    for (int t = 0; t < DE * NH; t++) w[t] = we[t];

    float4 ad4 = *(const float4*)&a_d[n * 4];

    // self-loop logit
    float ls[4];
    {
        float4 as4 = *(const float4*)&a_s[n * 4];
        const float* la = &lattr[(size_t)n * DE];
        float ae[4] = {0.f, 0.f, 0.f, 0.f};
#pragma unroll
        for (int k = 0; k < DE; k++) {
            float lv = la[k];
#pragma unroll
            for (int h = 0; h < 4; h++) ae[h] += lv * w[k * 4 + h];
        }
        ls[0] = as4.x + ad4.x + ae[0];
        ls[1] = as4.y + ad4.y + ae[1];
        ls[2] = as4.z + ad4.z + ae[2];
        ls[3] = as4.w + ad4.w + ae[3];
#pragma unroll
        for (int h = 0; h < 4; h++) ls[h] = ls[h] > 0.f ? ls[h] : NEGSL * ls[h];
    }
    float mx[4] = {ls[0], ls[1], ls[2], ls[3]};

    // pass 1: max over in-edges
    for (int e = lo; e < hi; e++) {
        int2 p = csr[e];
        float4 as4 = *(const float4*)&a_s[p.x * 4];
        const float* ea = &eattr[(size_t)p.y * DE];
        float l[4];
        l[0] = as4.x + ad4.x; l[1] = as4.y + ad4.y;
        l[2] = as4.z + ad4.z; l[3] = as4.w + ad4.w;
#pragma unroll
        for (int k = 0; k < DE; k++) {
            float ev = ea[k];
#pragma unroll
            for (int h = 0; h < 4; h++) l[h] += ev * w[k * 4 + h];
        }
#pragma unroll
        for (int h = 0; h < 4; h++) {
            float v = l[h] > 0.f ? l[h] : NEGSL * l[h];
            mx[h] = fmaxf(mx[h], v);
        }
    }

    // pass 2: exp, denom, weighted accumulate
    float den = 0.f;
    float acc[8] = {0.f, 0.f, 0.f, 0.f, 0.f, 0.f, 0.f, 0.f};
    {
        float ex = __expf(ls[myh] - mx[myh]);
        den += ex;
        const float4* xr = (const float4*)(xh + (size_t)n * HID + lane * 8);
        float4 v0 = xr[0], v1 = xr[1];
        acc[0] += ex * v0.x; acc[1] += ex * v0.y; acc[2] += ex * v0.z; acc[3] += ex * v0.w;
        acc[4] += ex * v1.x; acc[5] += ex * v1.y; acc[6] += ex * v1.z; acc[7] += ex * v1.w;
    }
    for (int e = lo; e < hi; e++) {
        int2 p = csr[e];
        float4 as4 = *(const float4*)&a_s[p.x * 4];
        const float* ea = &eattr[(size_t)p.y * DE];
        float l[4];
        l[0] = as4.x + ad4.x; l[1] = as4.y + ad4.y;
        l[2] = as4.z + ad4.z; l[3] = as4.w + ad4.w;
#pragma unroll
        for (int k = 0; k < DE; k++) {
            float ev = ea[k];
#pragma unroll
            for (int h = 0; h < 4; h++) l[h] += ev * w[k * 4 + h];
        }
        float lm = l[myh] > 0.f ? l[myh] : NEGSL * l[myh];
        float ex = __expf(lm - mx[myh]);
        den += ex;
        const float4* xr = (const float4*)(xh + (size_t)p.x * HID + lane * 8);
        float4 v0 = xr[0], v1 = xr[1];
        acc[0] += ex * v0.x; acc[1] += ex * v0.y; acc[2] += ex * v0.z; acc[3] += ex * v0.w;
        acc[4] += ex * v1.x; acc[5] += ex * v1.y; acc[6] += ex * v1.z; acc[7] += ex * v1.w;
    }

    float inv = 1.f / den;
    float* orow = out + (size_t)n * HID + lane * 8;
    *(float4*)&orow[0] = make_float4(acc[0] * inv, acc[1] * inv, acc[2] * inv, acc[3] * inv);
    *(float4*)&orow[4] = make_float4(acc[4] * inv, acc[5] * inv, acc[6] * inv, acc[7] * inv);
}

// ---------------- batchnorm ---------------------------------------------------
__global__ void bn_reset_kernel(float* __restrict__ bnsum)
{
    int t = threadIdx.x;
    if (t < 2 * HID) bnsum[t] = 0.f;
}

__global__ void bn_stats_kernel(const float* __restrict__ out, const float* __restrict__ gb,
                                float* __restrict__ bnsum)
{
    int t = threadIdx.x;
    int r0 = blockIdx.x * 512;
    int r1 = min(r0 + 512, NNODE);
    float gbv = gb[t];
    float s = 0.f, s2 = 0.f;
    for (int r = r0; r < r1; r++) {
        float v = out[(size_t)r * HID + t] + gbv;
        s += v; s2 += v * v;
    }
    atomicAdd(&bnsum[t], s);
    atomicAdd(&bnsum[HID + t], s2);
}

__global__ void bn_finalize_kernel(const float* __restrict__ bnsum,
                                   const float* __restrict__ gamma, const float* __restrict__ beta,
                                   float* __restrict__ ab)
{
    int t = threadIdx.x;
    if (t >= HID) return;
    float mu  = bnsum[t] / (float)NNODE;
    float var = bnsum[HID + t] / (float)NNODE - mu * mu;
    float a = gamma[t] * rsqrtf(var + EPSV);
    ab[t] = a;
    ab[HID + t] = beta[t] - mu * a;
}

__global__ void bn_apply_kernel(const float* __restrict__ out, const float* __restrict__ gb,
                                const float* __restrict__ ab, const float* __restrict__ hprev,
                                float* __restrict__ hnxt, int res)
{
    int idx = blockIdx.x * blockDim.x + threadIdx.x;
    int c = threadIdx.x;
    float v = out[idx] + gb[c];
    v = v * ab[c] + ab[HID + c];
    v = fmaxf(v, 0.f);
    if (res) v += hprev[idx];
    hnxt[idx] = v;
}

// ---------------- pooling ------------------------------------------------------
__global__ void pool_kernel(const float* __restrict__ h, const int* __restrict__ bidx,
                            float* __restrict__ g)
{
    int b = blockIdx.x;
    int t = threadIdx.x;
    __shared__ int slo, shi;
    if (t == 0) {
        int lo = 0, hi = NNODE;
        while (lo < hi) { int mid = (lo + hi) >> 1; if (bidx[mid] < b) lo = mid + 1; else hi = mid; }
        slo = lo;
        hi = NNODE;
        while (lo < hi) { int mid = (lo + hi) >> 1; if (bidx[mid] < b + 1) lo = mid + 1; else hi = mid; }
        shi = lo;
    }
    __syncthreads();
    int lo = slo, hi = shi;
    float s = 0.f;
    for (int r = lo; r < hi; r++) s += h[(size_t)r * HID + t];
    g[b * HID + t] = s / fmaxf((float)(hi - lo), 1.f);
}

// ---------------- final dot with p_W3 ----------------------------------------
__global__ void final_kernel(const float* __restrict__ z2, const float* __restrict__ w3,
                             const float* __restrict__ b3, float* __restrict__ outp)
{
    int gw = (blockIdx.x * blockDim.x + threadIdx.x) >> 5;
    int lane = threadIdx.x & 31;
    if (gw >= NB) return;
    float v = z2[gw * 64 + lane] * w3[lane] + z2[gw * 64 + lane + 32] * w3[lane + 32];
#pragma unroll
    for (int o = 16; o; o >>= 1) v += __shfl_xor_sync(0xFFFFFFFFu, v, o);
    if (lane == 0) outp[gw] = v + b3[0];
}

// ---------------- host orchestration -----------------------------------------
extern "C" void kernel_launch(void* const* d_in, const int* in_sizes, int n_in,
                              void* d_out, int out_size)
{
    int o = (n_in >= 21) ? 0 : -1;
    const float* x      = (const float*)d_in[0];
    const int*   ei     = (const int*)  d_in[1];
    const float* eattr  = (const float*)d_in[2];
    const int*   bidx   = (const int*)  d_in[3];
    const float* in_W   = (const float*)d_in[5 + o];
    const float* in_b   = (const float*)d_in[6 + o];
    const float* gat_W  = (const float*)d_in[7 + o];
    const float* attS   = (const float*)d_in[8 + o];
    const float* attD   = (const float*)d_in[9 + o];
    const float* edge_W = (const float*)d_in[10 + o];
    const float* attE   = (const float*)d_in[11 + o];
    const float* gat_b  = (const float*)d_in[12 + o];
    const float* bn_g   = (const float*)d_in[13 + o];
    const float* bn_b   = (const float*)d_in[14 + o];
    const float* p_W1   = (const float*)d_in[15 + o];
    const float* p_b1   = (const float*)d_in[16 + o];
    const float* p_W2   = (const float*)d_in[17 + o];
    const float* p_b2   = (const float*)d_in[18 + o];
    const float* p_W3   = (const float*)d_in[19 + o];
    const float* p_b3   = (const float*)d_in[20 + o];
    float* outp = (float*)d_out;

    float *h0, *h1, *xh, *outb, *lattr, *deg, *as_, *ad_, *we,
          *bnsum, *bnab, *pool, *z1, *z2;
    int *indeg, *off, *cursor, *bsum;
    int2 *csr;
    cudaGetSymbolAddress((void**)&h0,    g_h0);
    cudaGetSymbolAddress((void**)&h1,    g_h1);
    cudaGetSymbolAddress((void**)&xh,    g_xh);
    cudaGetSymbolAddress((void**)&outb,  g_out);
    cudaGetSymbolAddress((void**)&lattr, g_lattr);
    cudaGetSymbolAddress((void**)&deg,   g_deg);
    cudaGetSymbolAddress((void**)&as_,   g_as);
    cudaGetSymbolAddress((void**)&ad_,   g_ad);
    cudaGetSymbolAddress((void**)&we,    g_we);
    cudaGetSymbolAddress((void**)&bnsum, g_bnsum);
    cudaGetSymbolAddress((void**)&bnab,  g_bnab);
    cudaGetSymbolAddress((void**)&pool,  g_pool);
    cudaGetSymbolAddress((void**)&z1,    g_z1);
    cudaGetSymbolAddress((void**)&z2,    g_z2);
    cudaGetSymbolAddress((void**)&indeg, g_indeg);
    cudaGetSymbolAddress((void**)&off,   g_off);
    cudaGetSymbolAddress((void**)&cursor,g_cursor);
    cudaGetSymbolAddress((void**)&bsum,  g_bsum);
    cudaGetSymbolAddress((void**)&csr,   g_csr);

    cudaFuncSetAttribute(gemm_tf32_kernel,
                         cudaFuncAttributeMaxDynamicSharedMemorySize, G_SMEM_BYTES);

    // self-loop edge attributes + in-degree
    cudaMemsetAsync(deg, 0, NNODE * sizeof(float));
    cudaMemsetAsync(lattr, 0, NNODE * DE * sizeof(float));
    cudaMemsetAsync(indeg, 0, NNODE * sizeof(int));
    edge_deg_kernel<<<(NEDGE + 255) / 256, 256>>>(ei, eattr, deg, lattr, indeg);
    loop_norm_kernel<<<(NNODE + 255) / 256, 256>>>(deg, lattr);

    // CSR build (dst-sorted edge list)
    scan_block_reduce<<<NSCAN_BLK, 256>>>(indeg, bsum);
    scan_bsum_kernel<<<1, 1024>>>(bsum);
    scan_offsets_kernel<<<NSCAN_BLK, 256>>>(indeg, bsum, off, cursor);
    csr_fill_kernel<<<(NEDGE + 255) / 256, 256>>>(ei, cursor, csr);

    // input projection
    gemm_tf32_kernel<<<dim3(HID / 128, (NNODE + 127) / 128), 256, G_SMEM_BYTES>>>(
        x, in_W, in_b, h0, NNODE, DIN, HID, 1);

    float* hcur = h0;
    float* hnxt = h1;
    for (int i = 0; i < NLAY; i++) {
        we_kernel<<<1, 32>>>(edge_W + (size_t)i * DE * HID, attE + i * NH * CC, we);
        gemm_tf32_kernel<<<dim3(HID / 128, (NNODE + 127) / 128), 256, G_SMEM_BYTES>>>(
            hcur, gat_W + (size_t)i * HID * HID, nullptr, xh, NNODE, HID, HID, 0);
        attn_node_kernel<<<(NNODE * NH * 32 + 255) / 256, 256>>>(
            xh, attS + i * NH * CC, attD + i * NH * CC, as_, ad_);
        bn_reset_kernel<<<1, 512>>>(bnsum);
        gat_aggregate_kernel<<<(NNODE * 32 + 255) / 256, 256>>>(
            csr, off, eattr, lattr, we, as_, ad_, xh, outb);
        bn_stats_kernel<<<(NNODE + 511) / 512, 256>>>(outb, gat_b + i * HID, bnsum);
        bn_finalize_kernel<<<1, 256>>>(bnsum, bn_g + i * HID, bn_b + i * HID, bnab);
        bn_apply_kernel<<<NNODE, 256>>>(outb, gat_b + i * HID, bnab, hcur, hnxt, i > 0 ? 1 : 0);
        float* t = hcur; hcur = hnxt; hnxt = t;
    }

    // global mean pool + predictor MLP
    pool_kernel<<<NB, 256>>>(hcur, bidx, pool);
    sgemm_kernel<<<dim3(1, (NB + 127) / 128), 256>>>(pool, p_W1, p_b1, z1, NB, HID, 128, 1);
    sgemm_kernel<<<dim3(1, (NB + 127) / 128), 256>>>(z1, p_W2, p_b2, z2, NB, 128, 64, 1);
    final_kernel<<<(NB * 32 + 255) / 256, 256>>>(z2, p_W3, p_b3, outp);
}

// round 5
// speedup vs baseline: 1.9976x; 1.1463x over previous
#include <cuda_runtime.h>
#include <cuda_bf16.h>
#include <math.h>
#include <stdint.h>

#define NNODE 150000
#define NEDGE 300000
#define NB    4096
#define DIN   155
#define KPADX 192           // DIN padded to 3*64
#define DE    6
#define HID   256
#define NH    4
#define CC    64
#define NLAY  4
#define NEGSL 0.2f
#define EPSV  1e-5f
#define NSCAN_BLK ((NNODE + 255) / 256)   // 586

// ---------------- scratch (static device globals; no allocation) -------------
__device__ float g_h0[NNODE*HID];
__device__ float g_h1[NNODE*HID];
__device__ float g_xh[NNODE*HID];
__device__ float g_out[NNODE*HID];
__device__ float g_lattr[NNODE*DE];
__device__ float g_deg[NNODE];
__device__ float g_as[NNODE*NH];
__device__ float g_ad[NNODE*NH];
__device__ float g_we[DE*NH];
__device__ float g_bnsum[2*HID];
__device__ float g_bnab[2*HID];
__device__ float g_pool[NB*HID];
__device__ float g_z1[NB*128];
__device__ float g_z2[NB*64];
// bf16 hi/lo planes (ping-pong) for tensor-core GEMM inputs
__device__ __align__(16) __nv_bfloat16 g_pAhi[NNODE*HID];
__device__ __align__(16) __nv_bfloat16 g_pAlo[NNODE*HID];
__device__ __align__(16) __nv_bfloat16 g_pBhi[NNODE*HID];
__device__ __align__(16) __nv_bfloat16 g_pBlo[NNODE*HID];
__device__ __align__(16) __nv_bfloat16 g_wtHi[HID*HID];
__device__ __align__(16) __nv_bfloat16 g_wtLo[HID*HID];
// CSR
__device__ int  g_indeg[NNODE];
__device__ int  g_off[NNODE + 1];
__device__ int  g_cursor[NNODE];
__device__ int  g_bsum[1024];
__device__ int2 g_csr[NEDGE];

// ---------------- helpers ----------------------------------------------------
__device__ __forceinline__ uint32_t smem_to_u32(const void* p) {
    uint32_t a;
    asm("{ .reg .u64 t; cvta.to.shared.u64 t, %1; cvt.u32.u64 %0, t; }" : "=r"(a) : "l"(p));
    return a;
}
__device__ __forceinline__ void cp_async16(uint32_t dst, const void* src, int bytes) {
    asm volatile("cp.async.cg.shared.global [%0], [%1], 16, %2;\n"
                 :: "r"(dst), "l"(src), "r"(bytes));
}
__device__ __forceinline__ void ldmx4(uint32_t r[4], uint32_t addr) {
    asm volatile("ldmatrix.sync.aligned.m8n8.x4.shared.b16 {%0,%1,%2,%3}, [%4];"
                 : "=r"(r[0]), "=r"(r[1]), "=r"(r[2]), "=r"(r[3]) : "r"(addr));
}
__device__ __forceinline__ void mma_bf16(float c[4], const uint32_t a[4],
                                         uint32_t b0, uint32_t b1) {
    asm volatile("mma.sync.aligned.m16n8k16.row.col.f32.bf16.bf16.f32 "
                 "{%0,%1,%2,%3},{%4,%5,%6,%7},{%8,%9},{%0,%1,%2,%3};\n"
                 : "+f"(c[0]), "+f"(c[1]), "+f"(c[2]), "+f"(c[3])
                 : "r"(a[0]), "r"(a[1]), "r"(a[2]), "r"(a[3]), "r"(b0), "r"(b1));
}

// ---------------- bf16 (3x-split) tensor-core GEMM ---------------------------
// C[M, 256] = act(A @ B + bias)
// A as bf16 hi/lo planes [M][lda]; B as transposed planes [256][lda] (W^T).
// D = Ah*Bh + Ah*Bl + Al*Bh, fp32 accumulate. Block tile 128x128, BK=64.
// Smem layout per buffer: Ahi(16K) Alo(16K) Bhi(16K) Blo(16K); rows of 128B,
// 16B units XOR-swizzled by row for conflict-free ldmatrix.
#define PL_BYTES 16384
#define BUF_BYTES (4*PL_BYTES)           // 65536
#define GB_SMEM (2*BUF_BYTES)            // 131072

__global__ __launch_bounds__(256, 1)
void gemm_bf16_kernel(const __nv_bfloat16* __restrict__ Ahi, const __nv_bfloat16* __restrict__ Alo,
                      const __nv_bfloat16* __restrict__ Bhi, const __nv_bfloat16* __restrict__ Blo,
                      int lda, int nkt, int M,
                      const float* __restrict__ bias, int doRelu,
                      float* __restrict__ outF,
                      __nv_bfloat16* __restrict__ outHi, __nv_bfloat16* __restrict__ outLo)
{
    extern __shared__ __align__(128) char smem[];
    const uint32_t sb = smem_to_u32(smem);
    const int tid = threadIdx.x, lane = tid & 31, wid = tid >> 5;
    const int wm = (wid & 3) * 32;        // warp row offset in 128
    const int wn = (wid >> 2) * 64;       // warp col offset in 128
    const int bm = blockIdx.y * 128;
    const int bn = blockIdx.x * 128;

    float c[2][8][4];
#pragma unroll
    for (int mi = 0; mi < 2; mi++)
#pragma unroll
        for (int ni = 0; ni < 8; ni++)
#pragma unroll
            for (int q = 0; q < 4; q++) c[mi][ni][q] = 0.f;

    auto loadTile = [&](int kt, int buf) {
        uint32_t base = sb + buf * BUF_BYTES;
        int k0 = kt * 64;
        // A planes: idx 0..2047 -> plane, row(0-127), unit(0-7)
#pragma unroll
        for (int i = 0; i < 8; i++) {
            int idx = tid + (i << 8);
            int plane = idx >> 10;
            int rc = idx & 1023, row = rc >> 3, u = rc & 7;
            const __nv_bfloat16* sp = plane ? Alo : Ahi;
            int gr = bm + row;
            int bytes = (gr < M) ? 16 : 0;
            const void* src = sp + (size_t)(gr < M ? gr : 0) * lda + k0 + u * 8;
            uint32_t dst = base + plane * PL_BYTES + row * 128 + ((u ^ (row & 7)) * 16);
            cp_async16(dst, src, bytes);
        }
        // B planes: rows are N (bn..bn+127)
#pragma unroll
        for (int i = 0; i < 8; i++) {
            int idx = tid + (i << 8);
            int plane = idx >> 10;
            int rc = idx & 1023, row = rc >> 3, u = rc & 7;
            const __nv_bfloat16* sp = plane ? Blo : Bhi;
            const void* src = sp + (size_t)(bn + row) * lda + k0 + u * 8;
            uint32_t dst = base + (2 + plane) * PL_BYTES + row * 128 + ((u ^ (row & 7)) * 16);
            cp_async16(dst, src, 16);
        }
        asm volatile("cp.async.commit_group;\n");
    };

    auto computeTile = [&](int buf) {
        uint32_t base = sb + buf * BUF_BYTES;
#pragma unroll
        for (int ks = 0; ks < 4; ks++) {
            // A fragments: [plane][mi][4]
            uint32_t a[2][2][4];
#pragma unroll
            for (int plane = 0; plane < 2; plane++)
#pragma unroll
                for (int mi = 0; mi < 2; mi++) {
                    int row = wm + mi * 16 + ((lane >> 3) & 1) * 8 + (lane & 7);
                    int u = 2 * ks + (lane >> 4);
                    uint32_t addr = base + plane * PL_BYTES + row * 128 + ((u ^ (row & 7)) * 16);
                    ldmx4(a[plane][mi], addr);
                }
            // B fragments: [plane][ng][4] ; ng = 16-col group
            uint32_t b[2][4][4];
#pragma unroll
            for (int plane = 0; plane < 2; plane++)
#pragma unroll
                for (int ng = 0; ng < 4; ng++) {
                    int n = wn + ng * 16 + (lane >> 4) * 8 + (lane & 7);
                    int u = 2 * ks + ((lane >> 3) & 1);
                    uint32_t addr = base + (2 + plane) * PL_BYTES + n * 128 + ((u ^ (n & 7)) * 16);
                    ldmx4(b[plane][ng], addr);
                }
#pragma unroll
            for (int mi = 0; mi < 2; mi++)
#pragma unroll
                for (int ni = 0; ni < 8; ni++) {
                    int ng = ni >> 1, hf = (ni & 1) * 2;
                    uint32_t bh0 = b[0][ng][hf], bh1 = b[0][ng][hf + 1];
                    uint32_t bl0 = b[1][ng][hf], bl1 = b[1][ng][hf + 1];
                    mma_bf16(c[mi][ni], a[0][mi], bh0, bh1);   // Ah*Bh
                    mma_bf16(c[mi][ni], a[0][mi], bl0, bl1);   // Ah*Bl
                    mma_bf16(c[mi][ni], a[1][mi], bh0, bh1);   // Al*Bh
                }
        }
    };

    loadTile(0, 0);
    for (int kt = 0; kt < nkt; kt++) {
        if (kt + 1 < nkt) {
            loadTile(kt + 1, (kt + 1) & 1);
            asm volatile("cp.async.wait_group 1;\n");
        } else {
            asm volatile("cp.async.wait_group 0;\n");
        }
        __syncthreads();
        computeTile(kt & 1);
        __syncthreads();
    }

    // epilogue
#pragma unroll
    for (int mi = 0; mi < 2; mi++) {
        int r0 = bm + wm + mi * 16 + (lane >> 2);
#pragma unroll
        for (int ni = 0; ni < 8; ni++) {
            int col = bn + wn + ni * 8 + (lane & 3) * 2;
            float bv0 = bias ? bias[col] : 0.f;
            float bv1 = bias ? bias[col + 1] : 0.f;
            float v0 = c[mi][ni][0] + bv0, v1 = c[mi][ni][1] + bv1;
            float v2 = c[mi][ni][2] + bv0, v3 = c[mi][ni][3] + bv1;
            if (doRelu) {
                v0 = fmaxf(v0, 0.f); v1 = fmaxf(v1, 0.f);
                v2 = fmaxf(v2, 0.f); v3 = fmaxf(v3, 0.f);
            }
            if (outF) {
                if (r0 < M)     *(float2*)&outF[(size_t)r0 * HID + col]       = make_float2(v0, v1);
                if (r0 + 8 < M) *(float2*)&outF[(size_t)(r0 + 8) * HID + col] = make_float2(v2, v3);
            } else {
                if (r0 < M) {
                    __nv_bfloat16 h0b = __float2bfloat16(v0), h1b = __float2bfloat16(v1);
                    outHi[(size_t)r0 * HID + col]     = h0b;
                    outHi[(size_t)r0 * HID + col + 1] = h1b;
                    outLo[(size_t)r0 * HID + col]     = __float2bfloat16(v0 - __bfloat162float(h0b));
                    outLo[(size_t)r0 * HID + col + 1] = __float2bfloat16(v1 - __bfloat162float(h1b));
                }
                if (r0 + 8 < M) {
                    __nv_bfloat16 h2b = __float2bfloat16(v2), h3b = __float2bfloat16(v3);
                    outHi[(size_t)(r0 + 8) * HID + col]     = h2b;
                    outHi[(size_t)(r0 + 8) * HID + col + 1] = h3b;
                    outLo[(size_t)(r0 + 8) * HID + col]     = __float2bfloat16(v2 - __bfloat162float(h2b));
                    outLo[(size_t)(r0 + 8) * HID + col + 1] = __float2bfloat16(v3 - __bfloat162float(h3b));
                }
            }
        }
    }
}

// ---------------- plane prep kernels -----------------------------------------
__global__ void prep_x_kernel(const float* __restrict__ x,
                              __nv_bfloat16* __restrict__ hi, __nv_bfloat16* __restrict__ lo)
{
    int idx = blockIdx.x * blockDim.x + threadIdx.x;
    if (idx >= NNODE * KPADX) return;
    int row = idx / KPADX, k = idx - row * KPADX;
    float v = (k < DIN) ? x[(size_t)row * DIN + k] : 0.f;
    __nv_bfloat16 h = __float2bfloat16(v);
    hi[idx] = h;
    lo[idx] = __float2bfloat16(v - __bfloat162float(h));
}

// W [K][256] fp32 -> Wt planes [256][Kpad] bf16 (zero pad k >= K)
__global__ void prep_wt_kernel(const float* __restrict__ W, int K, int Kpad,
                               __nv_bfloat16* __restrict__ hi, __nv_bfloat16* __restrict__ lo)
{
    int idx = blockIdx.x * blockDim.x + threadIdx.x;
    if (idx >= HID * Kpad) return;
    int n = idx / Kpad, k = idx - n * Kpad;
    float v = (k < K) ? W[(size_t)k * HID + n] : 0.f;
    __nv_bfloat16 h = __float2bfloat16(v);
    hi[idx] = h;
    lo[idx] = __float2bfloat16(v - __bfloat162float(h));
}

// ---------------- generic tiled SGEMM (small MLP matmuls) --------------------
__global__ __launch_bounds__(256)
void sgemm_kernel(const float* __restrict__ A, const float* __restrict__ B,
                  const float* __restrict__ bias, float* __restrict__ C,
                  int M, int K, int N, int doRelu)
{
    const int BM = 128, BN = 128, BK = 8;
    __shared__ float As[BK][BM + 4];
    __shared__ float Bs[BK][BN];
    int tid = threadIdx.x;
    int bm = blockIdx.y * BM, bn = blockIdx.x * BN;
    int ty = tid >> 4, tx = tid & 15;
    float acc[8][8];
#pragma unroll
    for (int i = 0; i < 8; i++)
#pragma unroll
        for (int j = 0; j < 8; j++) acc[i][j] = 0.f;

    for (int k0 = 0; k0 < K; k0 += BK) {
#pragma unroll
        for (int i = 0; i < 4; i++) {
            int l = tid + i * 256;
            int r = l >> 3, c = l & 7;
            int gr = bm + r, gc = k0 + c;
            As[c][r] = (gr < M && gc < K) ? A[(size_t)gr * K + gc] : 0.f;
        }
#pragma unroll
        for (int i = 0; i < 4; i++) {
            int l = tid + i * 256;
            int r = l >> 7, c = l & 127;
            int gr = k0 + r, gc = bn + c;
            Bs[r][c] = (gr < K && gc < N) ? B[(size_t)gr * N + gc] : 0.f;
        }
        __syncthreads();
#pragma unroll
        for (int k = 0; k < BK; k++) {
            float4 av0 = *(const float4*)&As[k][ty * 8];
            float4 av1 = *(const float4*)&As[k][ty * 8 + 4];
            float4 bv0 = *(const float4*)&Bs[k][tx * 8];
            float4 bv1 = *(const float4*)&Bs[k][tx * 8 + 4];
            float ar[8] = {av0.x, av0.y, av0.z, av0.w, av1.x, av1.y, av1.z, av1.w};
            float br[8] = {bv0.x, bv0.y, bv0.z, bv0.w, bv1.x, bv1.y, bv1.z, bv1.w};
#pragma unroll
            for (int i = 0; i < 8; i++)
#pragma unroll
                for (int j = 0; j < 8; j++) acc[i][j] += ar[i] * br[j];
        }
        __syncthreads();
    }
#pragma unroll
    for (int i = 0; i < 8; i++) {
        int gr = bm + ty * 8 + i;
        if (gr >= M) continue;
#pragma unroll
        for (int j = 0; j < 8; j++) {
            int gc = bn + tx * 8 + j;
            if (gc >= N) continue;
            float v = acc[i][j];
            if (bias) v += bias[gc];
            if (doRelu) v = fmaxf(v, 0.f);
            C[(size_t)gr * N + gc] = v;
        }
    }
}

// ---------------- self-loop attr + in-degree count ---------------------------
__global__ void edge_deg_kernel(const int* __restrict__ ei, const float* __restrict__ eattr,
                                float* __restrict__ deg, float* __restrict__ lattr,
                                int* __restrict__ indeg)
{
    int e = blockIdx.x * blockDim.x + threadIdx.x;
    if (e >= NEDGE) return;
    int d = ei[NEDGE + e];
    atomicAdd(&deg[d], 1.f);
    atomicAdd(&indeg[d], 1);
#pragma unroll
    for (int k = 0; k < DE; k++) atomicAdd(&lattr[d * DE + k], eattr[e * DE + k]);
}

__global__ void loop_norm_kernel(const float* __restrict__ deg, float* __restrict__ lattr)
{
    int n = blockIdx.x * blockDim.x + threadIdx.x;
    if (n >= NNODE) return;
    float inv = 1.f / fmaxf(deg[n], 1.f);
#pragma unroll
    for (int k = 0; k < DE; k++) lattr[n * DE + k] *= inv;
}

// ---------------- CSR build: scan + fill -------------------------------------
__global__ void scan_block_reduce(const int* __restrict__ cnt, int* __restrict__ bsum)
{
    __shared__ int s[256];
    int i = blockIdx.x * 256 + threadIdx.x;
    s[threadIdx.x] = (i < NNODE) ? cnt[i] : 0;
    __syncthreads();
    for (int o = 128; o; o >>= 1) {
        if (threadIdx.x < o) s[threadIdx.x] += s[threadIdx.x + o];
        __syncthreads();
    }
    if (threadIdx.x == 0) bsum[blockIdx.x] = s[0];
}

__global__ void scan_bsum_kernel(int* __restrict__ bsum)
{
    __shared__ int s[1024];
    int t = threadIdx.x;
    int v = (t < NSCAN_BLK) ? bsum[t] : 0;
    s[t] = v;
    for (int o = 1; o < 1024; o <<= 1) {
        __syncthreads();
        int u = (t >= o) ? s[t - o] : 0;
        __syncthreads();
        s[t] += u;
    }
    if (t < NSCAN_BLK) bsum[t] = s[t] - v;   // exclusive
}

__global__ void scan_offsets_kernel(const int* __restrict__ cnt, const int* __restrict__ bsum,
                                    int* __restrict__ off, int* __restrict__ cursor)
{
    __shared__ int s[256];
    int i = blockIdx.x * 256 + threadIdx.x;
    int v = (i < NNODE) ? cnt[i] : 0;
    s[threadIdx.x] = v;
    for (int o = 1; o < 256; o <<= 1) {
        __syncthreads();
        int u = (threadIdx.x >= o) ? s[threadIdx.x - o] : 0;
        __syncthreads();
        s[threadIdx.x] += u;
    }
    __syncthreads();
    int excl = s[threadIdx.x] - v + bsum[blockIdx.x];
    if (i < NNODE) { off[i] = excl; cursor[i] = excl; }
    if (i == NNODE - 1) off[NNODE] = excl + v;
}

__global__ void csr_fill_kernel(const int* __restrict__ ei, int* __restrict__ cursor,
                                int2* __restrict__ csr)
{
    int e = blockIdx.x * blockDim.x + threadIdx.x;
    if (e >= NEDGE) return;
    int d = ei[NEDGE + e];
    int pos = atomicAdd(&cursor[d], 1);
    csr[pos] = make_int2(ei[e], e);
}

// ---------------- per-layer: contracted edge attention weights ---------------
__global__ void we_kernel(const float* __restrict__ eW, const float* __restrict__ aE,
                          float* __restrict__ we)
{
    int t = threadIdx.x;
    if (t >= DE * NH) return;
    int k = t >> 2, hh = t & 3;
    float s = 0.f;
    for (int c = 0; c < CC; c++) s += eW[k * HID + hh * CC + c] * aE[hh * CC + c];
    we[t] = s;
}

// ---------------- node attention scalars a_s, a_d ----------------------------
__global__ void attn_node_kernel(const float* __restrict__ xh, const float* __restrict__ wsrc,
                                 const float* __restrict__ wdst,
                                 float* __restrict__ a_s, float* __restrict__ a_d)
{
    int gw = (blockIdx.x * blockDim.x + threadIdx.x) >> 5;
    int lane = threadIdx.x & 31;
    if (gw >= NNODE * NH) return;
    int n = gw >> 2, hh = gw & 3;
    const float* row = xh + (size_t)n * HID + hh * CC;
    const float* ws = wsrc + hh * CC;
    const float* wd = wdst + hh * CC;
    float v0 = row[lane], v1 = row[lane + 32];
    float s = v0 * ws[lane] + v1 * ws[lane + 32];
    float d = v0 * wd[lane] + v1 * wd[lane + 32];
#pragma unroll
    for (int o = 16; o; o >>= 1) {
        s += __shfl_xor_sync(0xFFFFFFFFu, s, o);
        d += __shfl_xor_sync(0xFFFFFFFFu, d, o);
    }
    if (lane == 0) { a_s[gw] = s; a_d[gw] = d; }
}

// ---------------- fused GAT softmax + aggregate (warp per dst node) ----------
__global__ __launch_bounds__(256)
void gat_aggregate_kernel(const int2* __restrict__ csr, const int* __restrict__ off,
                          const float* __restrict__ eattr, const float* __restrict__ lattr,
                          const float* __restrict__ we,
                          const float* __restrict__ a_s, const float* __restrict__ a_d,
                          const float* __restrict__ xh, float* __restrict__ out)
{
    int gw = (blockIdx.x * blockDim.x + threadIdx.x) >> 5;
    int lane = threadIdx.x & 31;
    if (gw >= NNODE) return;
    const int n = gw;
    const int lo = off[n], hi = off[n + 1];
    const int myh = lane >> 3;

    float w[DE * NH];
#pragma unroll
    for (int t = 0; t < DE * NH; t++) w[t] = we[t];

    float4 ad4 = *(const float4*)&a_d[n * 4];

    float ls[4];
    {
        float4 as4 = *(const float4*)&a_s[n * 4];
        const float* la = &lattr[(size_t)n * DE];
        float ae[4] = {0.f, 0.f, 0.f, 0.f};
#pragma unroll
        for (int k = 0; k < DE; k++) {
            float lv = la[k];
#pragma unroll
            for (int h = 0; h < 4; h++) ae[h] += lv * w[k * 4 + h];
        }
        ls[0] = as4.x + ad4.x + ae[0];
        ls[1] = as4.y + ad4.y + ae[1];
        ls[2] = as4.z + ad4.z + ae[2];
        ls[3] = as4.w + ad4.w + ae[3];
#pragma unroll
        for (int h = 0; h < 4; h++) ls[h] = ls[h] > 0.f ? ls[h] : NEGSL * ls[h];
    }
    float mx[4] = {ls[0], ls[1], ls[2], ls[3]};

    for (int e = lo; e < hi; e++) {
        int2 p = csr[e];
        float4 as4 = *(const float4*)&a_s[p.x * 4];
        const float* ea = &eattr[(size_t)p.y * DE];
        float l[4];
        l[0] = as4.x + ad4.x; l[1] = as4.y + ad4.y;
        l[2] = as4.z + ad4.z; l[3] = as4.w + ad4.w;
#pragma unroll
        for (int k = 0; k < DE; k++) {
            float ev = ea[k];
#pragma unroll
            for (int h = 0; h < 4; h++) l[h] += ev * w[k * 4 + h];
        }
#pragma unroll
        for (int h = 0; h < 4; h++) {
            float v = l[h] > 0.f ? l[h] : NEGSL * l[h];
            mx[h] = fmaxf(mx[h], v);
        }
    }

    float den = 0.f;
    float acc[8] = {0.f, 0.f, 0.f, 0.f, 0.f, 0.f, 0.f, 0.f};
    {
        float ex = __expf(ls[myh] - mx[myh]);
        den += ex;
        const float4* xr = (const float4*)(xh + (size_t)n * HID + lane * 8);
        float4 v0 = xr[0], v1 = xr[1];
        acc[0] += ex * v0.x; acc[1] += ex * v0.y; acc[2] += ex * v0.z; acc[3] += ex * v0.w;
        acc[4] += ex * v1.x; acc[5] += ex * v1.y; acc[6] += ex * v1.z; acc[7] += ex * v1.w;
    }
    for (int e = lo; e < hi; e++) {
        int2 p = csr[e];
        float4 as4 = *(const float4*)&a_s[p.x * 4];
        const float* ea = &eattr[(size_t)p.y * DE];
        float l[4];
        l[0] = as4.x + ad4.x; l[1] = as4.y + ad4.y;
        l[2] = as4.z + ad4.z; l[3] = as4.w + ad4.w;
#pragma unroll
        for (int k = 0; k < DE; k++) {
            float ev = ea[k];
#pragma unroll
            for (int h = 0; h < 4; h++) l[h] += ev * w[k * 4 + h];
        }
        float lm = l[myh] > 0.f ? l[myh] : NEGSL * l[myh];
        float ex = __expf(lm - mx[myh]);
        den += ex;
        const float4* xr = (const float4*)(xh + (size_t)p.x * HID + lane * 8);
        float4 v0 = xr[0], v1 = xr[1];
        acc[0] += ex * v0.x; acc[1] += ex * v0.y; acc[2] += ex * v0.z; acc[3] += ex * v0.w;
        acc[4] += ex * v1.x; acc[5] += ex * v1.y; acc[6] += ex * v1.z; acc[7] += ex * v1.w;
    }

    float inv = 1.f / den;
    float* orow = out + (size_t)n * HID + lane * 8;
    *(float4*)&orow[0] = make_float4(acc[0] * inv, acc[1] * inv, acc[2] * inv, acc[3] * inv);
    *(float4*)&orow[4] = make_float4(acc[4] * inv, acc[5] * inv, acc[6] * inv, acc[7] * inv);
}

// ---------------- batchnorm ---------------------------------------------------
__global__ void bn_reset_kernel(float* __restrict__ bnsum)
{
    int t = threadIdx.x;
    if (t < 2 * HID) bnsum[t] = 0.f;
}

__global__ void bn_stats_kernel(const float* __restrict__ out, const float* __restrict__ gb,
                                float* __restrict__ bnsum)
{
    int t = threadIdx.x;
    int r0 = blockIdx.x * 512;
    int r1 = min(r0 + 512, NNODE);
    float gbv = gb[t];
    float s = 0.f, s2 = 0.f;
    for (int r = r0; r < r1; r++) {
        float v = out[(size_t)r * HID + t] + gbv;
        s += v; s2 += v * v;
    }
    atomicAdd(&bnsum[t], s);
    atomicAdd(&bnsum[HID + t], s2);
}

__global__ void bn_finalize_kernel(const float* __restrict__ bnsum,
                                   const float* __restrict__ gamma, const float* __restrict__ beta,
                                   float* __restrict__ ab)
{
    int t = threadIdx.x;
    if (t >= HID) return;
    float mu  = bnsum[t] / (float)NNODE;
    float var = bnsum[HID + t] / (float)NNODE - mu * mu;
    float a = gamma[t] * rsqrtf(var + EPSV);
    ab[t] = a;
    ab[HID + t] = beta[t] - mu * a;
}

// fused: bn affine + relu + residual -> fp32 h AND bf16 hi/lo planes
__global__ void bn_apply_kernel(const float* __restrict__ out, const float* __restrict__ gb,
                                const float* __restrict__ ab, const float* __restrict__ hprev,
                                float* __restrict__ hnxt, int res,
                                __nv_bfloat16* __restrict__ pHi, __nv_bfloat16* __restrict__ pLo)
{
    int idx = blockIdx.x * blockDim.x + threadIdx.x;
    int c = threadIdx.x;
    float v = out[idx] + gb[c];
    v = v * ab[c] + ab[HID + c];
    v = fmaxf(v, 0.f);
    if (res) v += hprev[idx];
    hnxt[idx] = v;
    __nv_bfloat16 h = __float2bfloat16(v);
    pHi[idx] = h;
    pLo[idx] = __float2bfloat16(v - __bfloat162float(h));
}

// ---------------- pooling ------------------------------------------------------
__global__ void pool_kernel(const float* __restrict__ h, const int* __restrict__ bidx,
                            float* __restrict__ g)
{
    int b = blockIdx.x;
    int t = threadIdx.x;
    __shared__ int slo, shi;
    if (t == 0) {
        int lo = 0, hi = NNODE;
        while (lo < hi) { int mid = (lo + hi) >> 1; if (bidx[mid] < b) lo = mid + 1; else hi = mid; }
        slo = lo;
        hi = NNODE;
        while (lo < hi) { int mid = (lo + hi) >> 1; if (bidx[mid] < b + 1) lo = mid + 1; else hi = mid; }
        shi = lo;
    }
    __syncthreads();
    int lo = slo, hi = shi;
    float s = 0.f;
    for (int r = lo; r < hi; r++) s += h[(size_t)r * HID + t];
    g[b * HID + t] = s / fmaxf((float)(hi - lo), 1.f);
}

// ---------------- final dot with p_W3 ----------------------------------------
__global__ void final_kernel(const float* __restrict__ z2, const float* __restrict__ w3,
                             const float* __restrict__ b3, float* __restrict__ outp)
{
    int gw = (blockIdx.x * blockDim.x + threadIdx.x) >> 5;
    int lane = threadIdx.x & 31;
    if (gw >= NB) return;
    float v = z2[gw * 64 + lane] * w3[lane] + z2[gw * 64 + lane + 32] * w3[lane + 32];
#pragma unroll
    for (int o = 16; o; o >>= 1) v += __shfl_xor_sync(0xFFFFFFFFu, v, o);
    if (lane == 0) outp[gw] = v + b3[0];
}

// ---------------- host orchestration -----------------------------------------
extern "C" void kernel_launch(void* const* d_in, const int* in_sizes, int n_in,
                              void* d_out, int out_size)
{
    int o = (n_in >= 21) ? 0 : -1;
    const float* x      = (const float*)d_in[0];
    const int*   ei     = (const int*)  d_in[1];
    const float* eattr  = (const float*)d_in[2];
    const int*   bidx   = (const int*)  d_in[3];
    const float* in_W   = (const float*)d_in[5 + o];
    const float* in_b   = (const float*)d_in[6 + o];
    const float* gat_W  = (const float*)d_in[7 + o];
    const float* attS   = (const float*)d_in[8 + o];
    const float* attD   = (const float*)d_in[9 + o];
    const float* edge_W = (const float*)d_in[10 + o];
    const float* attE   = (const float*)d_in[11 + o];
    const float* gat_b  = (const float*)d_in[12 + o];
    const float* bn_g   = (const float*)d_in[13 + o];
    const float* bn_b   = (const float*)d_in[14 + o];
    const float* p_W1   = (const float*)d_in[15 + o];
    const float* p_b1   = (const float*)d_in[16 + o];
    const float* p_W2   = (const float*)d_in[17 + o];
    const float* p_b2   = (const float*)d_in[18 + o];
    const float* p_W3   = (const float*)d_in[19 + o];
    const float* p_b3   = (const float*)d_in[20 + o];
    float* outp = (float*)d_out;

    float *h0, *h1, *xh, *outb, *lattr, *deg, *as_, *ad_, *we,
          *bnsum, *bnab, *pool, *z1, *z2;
    __nv_bfloat16 *pAhi, *pAlo, *pBhi, *pBlo, *wtHi, *wtLo;
    int *indeg, *off, *cursor, *bsum;
    int2 *csr;
    cudaGetSymbolAddress((void**)&h0,    g_h0);
    cudaGetSymbolAddress((void**)&h1,    g_h1);
    cudaGetSymbolAddress((void**)&xh,    g_xh);
    cudaGetSymbolAddress((void**)&outb,  g_out);
    cudaGetSymbolAddress((void**)&lattr, g_lattr);
    cudaGetSymbolAddress((void**)&deg,   g_deg);
    cudaGetSymbolAddress((void**)&as_,   g_as);
    cudaGetSymbolAddress((void**)&ad_,   g_ad);
    cudaGetSymbolAddress((void**)&we,    g_we);
    cudaGetSymbolAddress((void**)&bnsum, g_bnsum);
    cudaGetSymbolAddress((void**)&bnab,  g_bnab);
    cudaGetSymbolAddress((void**)&pool,  g_pool);
    cudaGetSymbolAddress((void**)&z1,    g_z1);
    cudaGetSymbolAddress((void**)&z2,    g_z2);
    cudaGetSymbolAddress((void**)&pAhi,  g_pAhi);
    cudaGetSymbolAddress((void**)&pAlo,  g_pAlo);
    cudaGetSymbolAddress((void**)&pBhi,  g_pBhi);
    cudaGetSymbolAddress((void**)&pBlo,  g_pBlo);
    cudaGetSymbolAddress((void**)&wtHi,  g_wtHi);
    cudaGetSymbolAddress((void**)&wtLo,  g_wtLo);
    cudaGetSymbolAddress((void**)&indeg, g_indeg);
    cudaGetSymbolAddress((void**)&off,   g_off);
    cudaGetSymbolAddress((void**)&cursor,g_cursor);
    cudaGetSymbolAddress((void**)&bsum,  g_bsum);
    cudaGetSymbolAddress((void**)&csr,   g_csr);

    cudaFuncSetAttribute(gemm_bf16_kernel,
                         cudaFuncAttributeMaxDynamicSharedMemorySize, GB_SMEM);

    const int NTILE = (NNODE + 127) / 128;   // 1172

    // self-loop edge attributes + in-degree
    cudaMemsetAsync(deg, 0, NNODE * sizeof(float));
    cudaMemsetAsync(lattr, 0, NNODE * DE * sizeof(float));
    cudaMemsetAsync(indeg, 0, NNODE * sizeof(int));
    edge_deg_kernel<<<(NEDGE + 255) / 256, 256>>>(ei, eattr, deg, lattr, indeg);
    loop_norm_kernel<<<(NNODE + 255) / 256, 256>>>(deg, lattr);

    // CSR build
    scan_block_reduce<<<NSCAN_BLK, 256>>>(indeg, bsum);
    scan_bsum_kernel<<<1, 1024>>>(bsum);
    scan_offsets_kernel<<<NSCAN_BLK, 256>>>(indeg, bsum, off, cursor);
    csr_fill_kernel<<<(NEDGE + 255) / 256, 256>>>(ei, cursor, csr);

    // input projection on tensor cores: x planes (pB), W_in^T planes -> h planes (pA)
    prep_x_kernel<<<(NNODE * KPADX + 255) / 256, 256>>>(x, pBhi, pBlo);
    prep_wt_kernel<<<(HID * KPADX + 255) / 256, 256>>>(in_W, DIN, KPADX, wtHi, wtLo);
    gemm_bf16_kernel<<<dim3(2, NTILE), 256, GB_SMEM>>>(pBhi, pBlo, wtHi, wtLo, KPADX, 3, NNODE,
                                                       in_b, 1, nullptr, pAhi, pAlo);

    float* hcur = h0;
    float* hnxt = h1;
    __nv_bfloat16 *pinHi = pAhi, *pinLo = pAlo;
    for (int i = 0; i < NLAY; i++) {
        we_kernel<<<1, 32>>>(edge_W + (size_t)i * DE * HID, attE + i * NH * CC, we);
        prep_wt_kernel<<<(HID * HID + 255) / 256, 256>>>(gat_W + (size_t)i * HID * HID,
                                                         HID, HID, wtHi, wtLo);
        gemm_bf16_kernel<<<dim3(2, NTILE), 256, GB_SMEM>>>(pinHi, pinLo, wtHi, wtLo, HID, 4, NNODE,
                                                           nullptr, 0, xh, nullptr, nullptr);
        attn_node_kernel<<<(NNODE * NH * 32 + 255) / 256, 256>>>(
            xh, attS + i * NH * CC, attD + i * NH * CC, as_, ad_);
        bn_reset_kernel<<<1, 512>>>(bnsum);
        gat_aggregate_kernel<<<(NNODE * 32 + 255) / 256, 256>>>(
            csr, off, eattr, lattr, we, as_, ad_, xh, outb);
        bn_stats_kernel<<<(NNODE + 511) / 512, 256>>>(outb, gat_b + i * HID, bnsum);
        bn_finalize_kernel<<<1, 256>>>(bnsum, bn_g + i * HID, bn_b + i * HID, bnab);
        __nv_bfloat16* poHi = (i & 1) ? pAhi : pBhi;
        __nv_bfloat16* poLo = (i & 1) ? pAlo : pBlo;
        bn_apply_kernel<<<NNODE, 256>>>(outb, gat_b + i * HID, bnab, hcur, hnxt,
                                        i > 0 ? 1 : 0, poHi, poLo);
        float* t = hcur; hcur = hnxt; hnxt = t;
        pinHi = poHi; pinLo = poLo;
    }

    // global mean pool + predictor MLP
    pool_kernel<<<NB, 256>>>(hcur, bidx, pool);
    sgemm_kernel<<<dim3(1, (NB + 127) / 128), 256>>>(pool, p_W1, p_b1, z1, NB, HID, 128, 1);
    sgemm_kernel<<<dim3(1, (NB + 127) / 128), 256>>>(z1, p_W2, p_b2, z2, NB, 128, 64, 1);
    final_kernel<<<(NB * 32 + 255) / 256, 256>>>(z2, p_W3, p_b3, outp);
}